// round 11
// baseline (speedup 1.0000x reference)
#include <cuda_runtime.h>

#define BB 64
#define TT 200
#define NS 1000

// ---------------- device scratch ----------------
__device__ float2 g_Wsk[1000 * 32];   // (w[l], w[l+32]) per skill, softmaxed
__device__ float2 g_EA [2000 * 64];   // (e, a) per x-index, per d
__device__ float2 g_G  [1000 * 32];   // (g[l], g[l+32]) = k·fW2^T + fb
__device__ int    g_idx[BB * TT];     // skill | (x << 16)
__device__ float  g_read[BB * TT * 64];
__device__ int    g_done[BB];         // per-batch scan-block completion count

static __device__ __forceinline__ float tanh_a(float x) {
    float y; asm("tanh.approx.f32 %0, %1;" : "=f"(y) : "f"(x)); return y;
}
static __device__ __forceinline__ float sigmoid_e(float x) {
    return 1.0f / (1.0f + __expf(-x));
}

// =====================================================================
// Kernel P: precompute tables. 1 row per warp. (R6/R8 version, 9.5us)
// Also resets g_done for this call (graph-replay safe).
// =====================================================================
__global__ __launch_bounds__(256) void k_pre(
    const int* __restrict__ skills, const int* __restrict__ responses,
    const float* __restrict__ k_emb, const float* __restrict__ v_emb,
    const float* __restrict__ Mk, const float* __restrict__ fW,
    const float* __restrict__ fb, const float* __restrict__ eW,
    const float* __restrict__ eb, const float* __restrict__ aW,
    const float* __restrict__ ab)
{
    __shared__ __align__(16) float W0[64 * 68];
    __shared__ __align__(16) float W1[64 * 68];

    int tid = threadIdx.x;
    int w = tid >> 5, l = tid & 31;
    bool isA = blockIdx.x < 125;
    int row = isA ? (blockIdx.x * 8 + w) : ((blockIdx.x - 125) * 8 + w);

    if (blockIdx.x == 0 && tid < BB) g_done[tid] = 0;

    const float4* xp = isA ? (const float4*)&k_emb[row * 64]
                           : (const float4*)&v_emb[row * 64];
    float4 xr[16];
#pragma unroll
    for (int q = 0; q < 16; q++) xr[q] = xp[q];

    int gt = blockIdx.x * 256 + tid;
    if (gt < BB * TT) {
        int s = skills[gt], r = responses[gt];
        int mr = (r > -1) ? r : 0;
        g_idx[gt] = s | ((s + NS * mr) << 16);
    }

    {
        const float4* s0 = isA ? (const float4*)Mk : (const float4*)eW;
        const float4* s1f = (const float4*)fW;
        const float4* s1a = (const float4*)aW;
        float4 v0[4], v1[4];
#pragma unroll
        for (int k = 0; k < 4; k++) {
            int i = tid + k * 256;
            int o = i >> 4, q4 = i & 15;
            v0[k] = s0[i];
            v1[k] = isA ? s1f[o * 32 + 16 + q4] : s1a[i];
        }
#pragma unroll
        for (int k = 0; k < 4; k++) {
            int i = tid + k * 256;
            int o = i >> 4, q4 = i & 15;
            *(float4*)&W0[o * 68 + q4 * 4] = v0[k];
            *(float4*)&W1[o * 68 + q4 * 4] = v1[k];
        }
    }
    __syncthreads();

    const float4* pL0 = (const float4*)&W0[l * 68];
    const float4* pH0 = (const float4*)&W0[(l + 32) * 68];
    const float4* pL1 = (const float4*)&W1[l * 68];
    const float4* pH1 = (const float4*)&W1[(l + 32) * 68];

    float c0A = 0.f, c1A = 0.f, c2A = 0.f, c3A = 0.f;
    float c0B = 0.f, c1B = 0.f, c2B = 0.f, c3B = 0.f;
#pragma unroll
    for (int q = 0; q < 16; q += 2) {
        float4 xa = xr[q];
        float4 xb = xr[q + 1];
        float4 aL = pL0[q];  float4 aL2 = pL0[q + 1];
        float4 aH = pH0[q];  float4 aH2 = pH0[q + 1];
        float4 bL = pL1[q];  float4 bL2 = pL1[q + 1];
        float4 bH = pH1[q];  float4 bH2 = pH1[q + 1];
        c0A = fmaf(xa.x, aL.x, c0A); c0A = fmaf(xa.y, aL.y, c0A);
        c0A = fmaf(xa.z, aL.z, c0A); c0A = fmaf(xa.w, aL.w, c0A);
        c1A = fmaf(xa.x, aH.x, c1A); c1A = fmaf(xa.y, aH.y, c1A);
        c1A = fmaf(xa.z, aH.z, c1A); c1A = fmaf(xa.w, aH.w, c1A);
        c2A = fmaf(xa.x, bL.x, c2A); c2A = fmaf(xa.y, bL.y, c2A);
        c2A = fmaf(xa.z, bL.z, c2A); c2A = fmaf(xa.w, bL.w, c2A);
        c3A = fmaf(xa.x, bH.x, c3A); c3A = fmaf(xa.y, bH.y, c3A);
        c3A = fmaf(xa.z, bH.z, c3A); c3A = fmaf(xa.w, bH.w, c3A);
        c0B = fmaf(xb.x, aL2.x, c0B); c0B = fmaf(xb.y, aL2.y, c0B);
        c0B = fmaf(xb.z, aL2.z, c0B); c0B = fmaf(xb.w, aL2.w, c0B);
        c1B = fmaf(xb.x, aH2.x, c1B); c1B = fmaf(xb.y, aH2.y, c1B);
        c1B = fmaf(xb.z, aH2.z, c1B); c1B = fmaf(xb.w, aH2.w, c1B);
        c2B = fmaf(xb.x, bL2.x, c2B); c2B = fmaf(xb.y, bL2.y, c2B);
        c2B = fmaf(xb.z, bL2.z, c2B); c2B = fmaf(xb.w, bL2.w, c2B);
        c3B = fmaf(xb.x, bH2.x, c3B); c3B = fmaf(xb.y, bH2.y, c3B);
        c3B = fmaf(xb.z, bH2.z, c3B); c3B = fmaf(xb.w, bH2.w, c3B);
    }
    float c0 = c0A + c0B, c1 = c1A + c1B;
    float c2 = c2A + c2B, c3 = c3A + c3B;

    if (isA) {
        float e0 = __expf(c0), e1 = __expf(c1);
        float s = e0 + e1;
#pragma unroll
        for (int o = 16; o; o >>= 1) s += __shfl_xor_sync(~0u, s, o);
        float inv = 1.0f / s;
        g_Wsk[row * 32 + l] = make_float2(e0 * inv, e1 * inv);
        g_G[row * 32 + l]   = make_float2(c2 + fb[l], c3 + fb[l + 32]);
    } else {
        g_EA[row * 64 + l]      = make_float2(sigmoid_e(c0 + eb[l]),      tanhf(c2 + ab[l]));
        g_EA[row * 64 + l + 32] = make_float2(sigmoid_e(c1 + eb[l + 32]), tanhf(c3 + ab[l + 32]));
    }
}

// =====================================================================
// Kernel S (fused, smem-unioned): R8 scan body verbatim; per-batch
// atomic gate; last block of each batch reuses the SAME smem for the
// output tail. Total smem stays ~38KB -> single wave at >=4 blocks/SM.
// =====================================================================
__global__ __launch_bounds__(256, 4) void k_scan(
    const float* __restrict__ Mv0, const float* __restrict__ fW,
    const float* __restrict__ pW,  const float* __restrict__ pb,
    float* __restrict__ out)
{
    // union region: scan uses [w_s 16384 | ea_s 4096 | buf 18432] = 38912 B
    //               tail uses [F1 17408 | x_s 4096]              = 21504 B
    __shared__ __align__(16) char sm[38912];
    __shared__ int is_last;

    float2 (*w_s)[32][32] = reinterpret_cast<float2(*)[32][32]>(sm);
    float2 (*ea_s)[32][8] = reinterpret_cast<float2(*)[32][8]>(sm + 16384);
    float  (*buf)[16][36] = reinterpret_cast<float(*)[16][36]>(sm + 20480);

    int tid = threadIdx.x;
    int w = tid >> 5, l = tid & 31;
    int b = blockIdx.x >> 3;
    int dbase = (blockIdx.x & 7) << 3;
    int d = dbase + w;

    float s0 = Mv0[l * 64 + d];
    float s1 = Mv0[(l + 32) * 64 + d];

    const int* idxp = g_idx + b * TT;
    float* rd = g_read + b * TT * 64 + d;
    float (*mybuf)[36] = buf[w];

    int est = tid >> 3, edl = tid & 7;

    float2 wv[4], eav;
#pragma unroll
    for (int k = 0; k < 4; k++) {
        int p = idxp[w + 8 * k];
        wv[k] = g_Wsk[(p & 0xffff) * 32 + l];
    }
    {
        int pe = idxp[est];
        eav = g_EA[(pe >> 16) * 64 + dbase + edl];
    }
#pragma unroll
    for (int k = 0; k < 4; k++) w_s[0][w + 8 * k][l] = wv[k];
    ea_s[0][est][edl] = eav;
    __syncthreads();

    for (int c = 0; c < 6; c++) {
        int cur = c & 1;
        if (c < 5) {
            int t0n = (c + 1) * 32;
#pragma unroll
            for (int k = 0; k < 4; k++) {
                int p = idxp[t0n + w + 8 * k];
                wv[k] = g_Wsk[(p & 0xffff) * 32 + l];
            }
            int pe = idxp[t0n + est];
            eav = g_EA[(pe >> 16) * 64 + dbase + edl];
        } else {
#pragma unroll
            for (int k = 0; k < 4; k++) {
                int st = w + 8 * k; st = st < 8 ? st : 7;
                int p = idxp[192 + st];
                wv[k] = g_Wsk[(p & 0xffff) * 32 + l];
            }
            int st2 = est < 8 ? est : 7;
            int pe = idxp[192 + st2];
            eav = g_EA[(pe >> 16) * 64 + dbase + edl];
        }

        int t0 = c * 32;
#pragma unroll
        for (int h = 0; h < 2; h++) {
#pragma unroll
            for (int j = 0; j < 16; j++) {
                int t = h * 16 + j;
                float2 w2 = w_s[cur][t][l];
                float2 ea = ea_s[cur][t][w];
                float r = w2.x * s0 + w2.y * s1;          // read BEFORE update
                s0 = fmaf(w2.x, fmaf(-ea.x, s0, ea.y), s0);
                s1 = fmaf(w2.y, fmaf(-ea.x, s1, ea.y), s1);
                mybuf[j][l] = r;
            }
            __syncwarp();
            if (l < 16) {
                const float4* rowp = (const float4*)&mybuf[l][0];
                float sum = 0.f;
#pragma unroll
                for (int k = 0; k < 8; k++) {
                    float4 v = rowp[k];
                    sum += (v.x + v.y) + (v.z + v.w);
                }
                rd[(t0 + h * 16 + l) * 64] = sum;
            }
            __syncwarp();
        }

        int nb = cur ^ 1;
#pragma unroll
        for (int k = 0; k < 4; k++) w_s[nb][w + 8 * k][l] = wv[k];
        ea_s[nb][est][edl] = eav;
        __syncthreads();
    }

    // tail of the scan: 8 steps from buffer 0
    {
#pragma unroll
        for (int j = 0; j < 8; j++) {
            float2 w2 = w_s[0][j][l];
            float2 ea = ea_s[0][j][w];
            float r = w2.x * s0 + w2.y * s1;
            s0 = fmaf(w2.x, fmaf(-ea.x, s0, ea.y), s0);
            s1 = fmaf(w2.y, fmaf(-ea.x, s1, ea.y), s1);
            mybuf[j][l] = r;
        }
        __syncwarp();
        if (l < 8) {
            const float4* rowp = (const float4*)&mybuf[l][0];
            float sum = 0.f;
#pragma unroll
            for (int k = 0; k < 8; k++) {
                float4 v = rowp[k];
                sum += (v.x + v.y) + (v.z + v.w);
            }
            rd[(192 + l) * 64] = sum;
        }
    }

    // ---------------- per-batch gate: last block computes the outputs ----
    __threadfence();                 // release our g_read writes
    __syncthreads();                 // all warps' writes issued before count
    if (tid == 0) {
        int old = atomicAdd(&g_done[b], 1);
        is_last = (old == 7);
    }
    __syncthreads();                 // also fences smem reuse below
    if (!is_last) return;
    __threadfence();                 // acquire: see other blocks' g_read

    // ---- output tail, reusing the SAME smem region ----
    float* F1 = reinterpret_cast<float*>(sm);                    // 64*68 floats
    float (*x_s)[2][64] = reinterpret_cast<float(*)[2][64]>(sm + 17408);

    {
        const float4* src = (const float4*)fW;
#pragma unroll
        for (int k = 0; k < 4; k++) {
            int i = tid + k * 256;
            int o = i >> 4, q4 = i & 15;
            *(float4*)&F1[o * 68 + q4 * 4] = src[o * 32 + q4];
        }
    }
    __syncthreads();

    const float4* pL = (const float4*)&F1[l * 68];
    const float4* pH = (const float4*)&F1[(l + 32) * 68];
    float pl = pW[l], ph = pW[l + 32];
    float pbv = pb[0];

    for (int pr = w; pr < 100; pr += 8) {
        int r0 = 2 * pr, r1 = 2 * pr + 1;       // batch-local out rows
        bool has1 = (r1 < 199);
        int i0 = b * TT + r0 + 1;
        int i1 = has1 ? (b * TT + r1 + 1) : i0;

        *(float2*)&x_s[w][0][2 * l] = ((const float2*)&g_read[i0 * 64])[l];
        *(float2*)&x_s[w][1][2 * l] = ((const float2*)&g_read[i1 * 64])[l];
        __syncwarp();

        float a00 = 0.f, a01 = 0.f, a10 = 0.f, a11 = 0.f;
#pragma unroll
        for (int q = 0; q < 16; q++) {
            float4 xa = *(const float4*)&x_s[w][0][q * 4];
            float4 xb = *(const float4*)&x_s[w][1][q * 4];
            float4 mL = pL[q];
            float4 mH = pH[q];
            a00 = fmaf(xa.x, mL.x, a00); a00 = fmaf(xa.y, mL.y, a00);
            a00 = fmaf(xa.z, mL.z, a00); a00 = fmaf(xa.w, mL.w, a00);
            a01 = fmaf(xa.x, mH.x, a01); a01 = fmaf(xa.y, mH.y, a01);
            a01 = fmaf(xa.z, mH.z, a01); a01 = fmaf(xa.w, mH.w, a01);
            a10 = fmaf(xb.x, mL.x, a10); a10 = fmaf(xb.y, mL.y, a10);
            a10 = fmaf(xb.z, mL.z, a10); a10 = fmaf(xb.w, mL.w, a10);
            a11 = fmaf(xb.x, mH.x, a11); a11 = fmaf(xb.y, mH.y, a11);
            a11 = fmaf(xb.z, mH.z, a11); a11 = fmaf(xb.w, mH.w, a11);
        }

        int sk0 = g_idx[i0] & 0xffff;
        int sk1 = g_idx[i1] & 0xffff;
        float2 G0 = g_G[sk0 * 32 + l];
        float2 G1 = g_G[sk1 * 32 + l];

        float f00 = tanh_a(a00 + G0.x), f01 = tanh_a(a01 + G0.y);
        float f10 = tanh_a(a10 + G1.x), f11 = tanh_a(a11 + G1.y);

        float r0v = f00 * pl + f01 * ph;
        float r1v = f10 * pl + f11 * ph;
#pragma unroll
        for (int o = 16; o; o >>= 1) {
            r0v += __shfl_xor_sync(~0u, r0v, o);
            r1v += __shfl_xor_sync(~0u, r1v, o);
        }
        if (l == 0) {
            out[b * 199 + r0] = sigmoid_e(r0v + pbv);
            if (has1) out[b * 199 + r1] = sigmoid_e(r1v + pbv);
        }
        __syncwarp();
    }
}

// =====================================================================
// launch
// =====================================================================
extern "C" void kernel_launch(void* const* d_in, const int* in_sizes, int n_in,
                              void* d_out, int out_size) {
    const int*   skills    = (const int*)d_in[0];
    const int*   responses = (const int*)d_in[1];
    const float* k_emb     = (const float*)d_in[2];
    const float* v_emb     = (const float*)d_in[3];
    const float* Mk        = (const float*)d_in[4];
    const float* Mv0       = (const float*)d_in[5];
    const float* fW        = (const float*)d_in[6];
    const float* fb        = (const float*)d_in[7];
    const float* eW        = (const float*)d_in[8];
    const float* eb        = (const float*)d_in[9];
    const float* aW        = (const float*)d_in[10];
    const float* ab        = (const float*)d_in[11];
    const float* pW        = (const float*)d_in[12];
    const float* pb        = (const float*)d_in[13];
    float* out = (float*)d_out;

    k_pre <<<375, 256>>>(skills, responses, k_emb, v_emb, Mk, fW, fb, eW, eb, aW, ab);
    k_scan<<<512, 256>>>(Mv0, fW, pW, pb, out);
}

// round 12
// speedup vs baseline: 1.8469x; 1.8469x over previous
#include <cuda_runtime.h>

#define BB 64
#define TT 200
#define NS 1000

// ---------------- device scratch ----------------
__device__ float2 g_Wsk[1000 * 32];   // (w[l], w[l+32]) per skill, softmaxed
__device__ float2 g_EA [2000 * 64];   // (e, a) per x-index, per d
__device__ float2 g_G  [1000 * 32];   // (g[l], g[l+32]) = k·fW2^T + fb
__device__ int    g_idx[BB * TT];     // skill | (x << 16)
__device__ float  g_read[BB * TT * 64];

static __device__ __forceinline__ float tanh_a(float x) {
    float y; asm("tanh.approx.f32 %0, %1;" : "=f"(y) : "f"(x)); return y;
}
static __device__ __forceinline__ float sigmoid_e(float x) {
    return 1.0f / (1.0f + __expf(-x));
}

// =====================================================================
// Kernel P: precompute tables. ONE ROW PER WARP-PAIR: warpA does the
// W0 GEMV (Mk or eW), warpB the W1 GEMV (fW2 or aW). 2x warps vs R8,
// half the per-warp FMA chain. EA combine via 1KB smem exchange.
//   blocks [0,250):   skill rows (4/block): Wsk, G
//   blocks [250,750): x rows (4/block):     EA
// =====================================================================
__global__ __launch_bounds__(256) void k_pre(
    const int* __restrict__ skills, const int* __restrict__ responses,
    const float* __restrict__ k_emb, const float* __restrict__ v_emb,
    const float* __restrict__ Mk, const float* __restrict__ fW,
    const float* __restrict__ fb, const float* __restrict__ eW,
    const float* __restrict__ eb, const float* __restrict__ aW,
    const float* __restrict__ ab)
{
    __shared__ __align__(16) float W0[64 * 68];
    __shared__ __align__(16) float W1[64 * 68];
    __shared__ __align__(16) float xch[4][64];

    int tid = threadIdx.x;
    int w = tid >> 5, l = tid & 31;
    int pair = w >> 1;            // 0..3 : row within block
    int mat  = w & 1;             // 0 -> W0 matrix, 1 -> W1 matrix
    bool isA = blockIdx.x < 250;
    int row = isA ? (blockIdx.x * 4 + pair) : ((blockIdx.x - 250) * 4 + pair);

    // 1) per-warp x-row gather FIRST (long-latency unique load)
    const float4* xp = isA ? (const float4*)&k_emb[row * 64]
                           : (const float4*)&v_emb[row * 64];
    float4 xr[16];
#pragma unroll
    for (int q = 0; q < 16; q++) xr[q] = xp[q];

    // 2) g_idx (blocks 0..49 cover all 12800)
    int gt = blockIdx.x * 256 + tid;
    if (gt < BB * TT) {
        int s = skills[gt], r = responses[gt];
        int mr = (r > -1) ? r : 0;
        g_idx[gt] = s | ((s + NS * mr) << 16);
    }

    // 3) weight staging (both matrices)
    {
        const float4* s0 = isA ? (const float4*)Mk : (const float4*)eW;
        const float4* s1f = (const float4*)fW;
        const float4* s1a = (const float4*)aW;
        float4 v0[4], v1[4];
#pragma unroll
        for (int k = 0; k < 4; k++) {
            int i = tid + k * 256;
            int o = i >> 4, q4 = i & 15;
            v0[k] = s0[i];
            v1[k] = isA ? s1f[o * 32 + 16 + q4] : s1a[i];
        }
#pragma unroll
        for (int k = 0; k < 4; k++) {
            int i = tid + k * 256;
            int o = i >> 4, q4 = i & 15;
            *(float4*)&W0[o * 68 + q4 * 4] = v0[k];
            *(float4*)&W1[o * 68 + q4 * 4] = v1[k];
        }
    }
    __syncthreads();

    // 4) GEMV on my matrix only: outputs (l, l+32)
    const float* Wm = mat ? W1 : W0;
    const float4* pL = (const float4*)&Wm[l * 68];
    const float4* pH = (const float4*)&Wm[(l + 32) * 68];

    float cLa = 0.f, cLb = 0.f, cHa = 0.f, cHb = 0.f;
#pragma unroll
    for (int q = 0; q < 16; q += 2) {
        float4 xa = xr[q];
        float4 xb = xr[q + 1];
        float4 mLa = pL[q]; float4 mLb = pL[q + 1];
        float4 mHa = pH[q]; float4 mHb = pH[q + 1];
        cLa = fmaf(xa.x, mLa.x, cLa); cLa = fmaf(xa.y, mLa.y, cLa);
        cLa = fmaf(xa.z, mLa.z, cLa); cLa = fmaf(xa.w, mLa.w, cLa);
        cHa = fmaf(xa.x, mHa.x, cHa); cHa = fmaf(xa.y, mHa.y, cHa);
        cHa = fmaf(xa.z, mHa.z, cHa); cHa = fmaf(xa.w, mHa.w, cHa);
        cLb = fmaf(xb.x, mLb.x, cLb); cLb = fmaf(xb.y, mLb.y, cLb);
        cLb = fmaf(xb.z, mLb.z, cLb); cLb = fmaf(xb.w, mLb.w, cLb);
        cHb = fmaf(xb.x, mHb.x, cHb); cHb = fmaf(xb.y, mHb.y, cHb);
        cHb = fmaf(xb.z, mHb.z, cHb); cHb = fmaf(xb.w, mHb.w, cHb);
    }
    float cl = cLa + cLb, ch = cHa + cHb;

    if (isA) {
        if (mat == 0) {
            // softmax over 64 logits (tiny logits; skip max-subtraction)
            float e0 = __expf(cl), e1 = __expf(ch);
            float s = e0 + e1;
#pragma unroll
            for (int o = 16; o; o >>= 1) s += __shfl_xor_sync(~0u, s, o);
            float inv = 1.0f / s;
            g_Wsk[row * 32 + l] = make_float2(e0 * inv, e1 * inv);
        } else {
            g_G[row * 32 + l] = make_float2(cl + fb[l], ch + fb[l + 32]);
        }
    } else {
        if (mat == 1) {
            xch[pair][l]      = tanhf(cl + ab[l]);
            xch[pair][l + 32] = tanhf(ch + ab[l + 32]);
        }
        __syncthreads();
        if (mat == 0) {
            g_EA[row * 64 + l]      = make_float2(sigmoid_e(cl + eb[l]),      xch[pair][l]);
            g_EA[row * 64 + l + 32] = make_float2(sigmoid_e(ch + eb[l + 32]), xch[pair][l + 32]);
        }
    }
}

// =====================================================================
// Kernel S: scan (R8 version verbatim). 4096 warps; block = 8 warps,
// same b, d = 8*(blk&7)+w. Register-pipelined double-buffered staging;
// LDS-only inner loop; deferred transposed read-reduction.
// =====================================================================
__global__ __launch_bounds__(256) void k_scan(const float* __restrict__ Mv0)
{
    __shared__ __align__(16) float2 w_s[2][32][32];   // 16KB
    __shared__ __align__(16) float2 ea_s[2][32][8];   //  4KB
    __shared__ __align__(16) float  buf[8][16][36];   // 18KB

    int tid = threadIdx.x;
    int w = tid >> 5, l = tid & 31;
    int b = blockIdx.x >> 3;
    int dbase = (blockIdx.x & 7) << 3;
    int d = dbase + w;

    float s0 = Mv0[l * 64 + d];
    float s1 = Mv0[(l + 32) * 64 + d];

    const int* idxp = g_idx + b * TT;
    float* rd = g_read + b * TT * 64 + d;
    float (*mybuf)[36] = buf[w];

    int est = tid >> 3, edl = tid & 7;

    float2 wv[4], eav;
#pragma unroll
    for (int k = 0; k < 4; k++) {
        int p = idxp[w + 8 * k];
        wv[k] = g_Wsk[(p & 0xffff) * 32 + l];
    }
    {
        int pe = idxp[est];
        eav = g_EA[(pe >> 16) * 64 + dbase + edl];
    }
#pragma unroll
    for (int k = 0; k < 4; k++) w_s[0][w + 8 * k][l] = wv[k];
    ea_s[0][est][edl] = eav;
    __syncthreads();

    for (int c = 0; c < 6; c++) {
        int cur = c & 1;
        if (c < 5) {
            int t0n = (c + 1) * 32;
#pragma unroll
            for (int k = 0; k < 4; k++) {
                int p = idxp[t0n + w + 8 * k];
                wv[k] = g_Wsk[(p & 0xffff) * 32 + l];
            }
            int pe = idxp[t0n + est];
            eav = g_EA[(pe >> 16) * 64 + dbase + edl];
        } else {
#pragma unroll
            for (int k = 0; k < 4; k++) {
                int st = w + 8 * k; st = st < 8 ? st : 7;
                int p = idxp[192 + st];
                wv[k] = g_Wsk[(p & 0xffff) * 32 + l];
            }
            int st2 = est < 8 ? est : 7;
            int pe = idxp[192 + st2];
            eav = g_EA[(pe >> 16) * 64 + dbase + edl];
        }

        int t0 = c * 32;
#pragma unroll
        for (int h = 0; h < 2; h++) {
#pragma unroll
            for (int j = 0; j < 16; j++) {
                int t = h * 16 + j;
                float2 w2 = w_s[cur][t][l];
                float2 ea = ea_s[cur][t][w];
                float r = w2.x * s0 + w2.y * s1;          // read BEFORE update
                s0 = fmaf(w2.x, fmaf(-ea.x, s0, ea.y), s0);
                s1 = fmaf(w2.y, fmaf(-ea.x, s1, ea.y), s1);
                mybuf[j][l] = r;
            }
            __syncwarp();
            if (l < 16) {
                const float4* rowp = (const float4*)&mybuf[l][0];
                float sum = 0.f;
#pragma unroll
                for (int k = 0; k < 8; k++) {
                    float4 v = rowp[k];
                    sum += (v.x + v.y) + (v.z + v.w);
                }
                rd[(t0 + h * 16 + l) * 64] = sum;
            }
            __syncwarp();
        }

        int nb = cur ^ 1;
#pragma unroll
        for (int k = 0; k < 4; k++) w_s[nb][w + 8 * k][l] = wv[k];
        ea_s[nb][est][edl] = eav;
        __syncthreads();
    }

    // tail: 8 steps from buffer 0
    {
#pragma unroll
        for (int j = 0; j < 8; j++) {
            float2 w2 = w_s[0][j][l];
            float2 ea = ea_s[0][j][w];
            float r = w2.x * s0 + w2.y * s1;
            s0 = fmaf(w2.x, fmaf(-ea.x, s0, ea.y), s0);
            s1 = fmaf(w2.y, fmaf(-ea.x, s1, ea.y), s1);
            mybuf[j][l] = r;
        }
        __syncwarp();
        if (l < 8) {
            const float4* rowp = (const float4*)&mybuf[l][0];
            float sum = 0.f;
#pragma unroll
            for (int k = 0; k < 8; k++) {
                float4 v = rowp[k];
                sum += (v.x + v.y) + (v.z + v.w);
            }
            rd[(192 + l) * 64] = sum;
        }
    }
}

// =====================================================================
// Kernel O: p = sigmoid( tanh(read·fW1^T + G[skill]) · pW^T + pb )
// (R8 version verbatim)
// =====================================================================
__global__ __launch_bounds__(256, 5) void k_out(
    const float* __restrict__ fW, const float* __restrict__ pW,
    const float* __restrict__ pb, float* __restrict__ out)
{
    __shared__ __align__(16) float F1[64 * 68];
    __shared__ __align__(16) float x_s[8][2][64];

    int tid = threadIdx.x;
    {
        const float4* src = (const float4*)fW;
#pragma unroll
        for (int k = 0; k < 4; k++) {
            int i = tid + k * 256;
            int o = i >> 4, q4 = i & 15;
            *(float4*)&F1[o * 68 + q4 * 4] = src[o * 32 + q4];
        }
    }
    __syncthreads();

    int w = tid >> 5, l = tid & 31;
    const float4* pL = (const float4*)&F1[l * 68];
    const float4* pH = (const float4*)&F1[(l + 32) * 68];
    float pl = pW[l], ph = pW[l + 32];
    float pbv = pb[0];

    for (int rp = 0; rp < 2; rp++) {
        int row0 = blockIdx.x * 32 + w * 4 + rp * 2;
        int row1 = row0 + 1;
        int b0 = row0 / 199, t0 = row0 - b0 * 199 + 1;
        int b1 = row1 / 199, t1 = row1 - b1 * 199 + 1;
        int i0 = b0 * TT + t0, i1 = b1 * TT + t1;

        *(float2*)&x_s[w][0][2 * l] = ((const float2*)&g_read[i0 * 64])[l];
        *(float2*)&x_s[w][1][2 * l] = ((const float2*)&g_read[i1 * 64])[l];
        __syncwarp();

        float a00 = 0.f, a01 = 0.f, a10 = 0.f, a11 = 0.f;
#pragma unroll
        for (int q = 0; q < 16; q++) {
            float4 xa = *(const float4*)&x_s[w][0][q * 4];
            float4 xb = *(const float4*)&x_s[w][1][q * 4];
            float4 mL = pL[q];
            float4 mH = pH[q];
            a00 = fmaf(xa.x, mL.x, a00); a00 = fmaf(xa.y, mL.y, a00);
            a00 = fmaf(xa.z, mL.z, a00); a00 = fmaf(xa.w, mL.w, a00);
            a01 = fmaf(xa.x, mH.x, a01); a01 = fmaf(xa.y, mH.y, a01);
            a01 = fmaf(xa.z, mH.z, a01); a01 = fmaf(xa.w, mH.w, a01);
            a10 = fmaf(xb.x, mL.x, a10); a10 = fmaf(xb.y, mL.y, a10);
            a10 = fmaf(xb.z, mL.z, a10); a10 = fmaf(xb.w, mL.w, a10);
            a11 = fmaf(xb.x, mH.x, a11); a11 = fmaf(xb.y, mH.y, a11);
            a11 = fmaf(xb.z, mH.z, a11); a11 = fmaf(xb.w, mH.w, a11);
        }

        int sk0 = g_idx[i0] & 0xffff;
        int sk1 = g_idx[i1] & 0xffff;
        float2 G0 = g_G[sk0 * 32 + l];
        float2 G1 = g_G[sk1 * 32 + l];

        float f00 = tanh_a(a00 + G0.x), f01 = tanh_a(a01 + G0.y);
        float f10 = tanh_a(a10 + G1.x), f11 = tanh_a(a11 + G1.y);

        float r0 = f00 * pl + f01 * ph;
        float r1 = f10 * pl + f11 * ph;
#pragma unroll
        for (int o = 16; o; o >>= 1) {
            r0 += __shfl_xor_sync(~0u, r0, o);
            r1 += __shfl_xor_sync(~0u, r1, o);
        }
        if (l == 0) {
            out[row0] = sigmoid_e(r0 + pbv);
            out[row1] = sigmoid_e(r1 + pbv);
        }
        __syncwarp();
    }
}

// =====================================================================
// launch
// =====================================================================
extern "C" void kernel_launch(void* const* d_in, const int* in_sizes, int n_in,
                              void* d_out, int out_size) {
    const int*   skills    = (const int*)d_in[0];
    const int*   responses = (const int*)d_in[1];
    const float* k_emb     = (const float*)d_in[2];
    const float* v_emb     = (const float*)d_in[3];
    const float* Mk        = (const float*)d_in[4];
    const float* Mv0       = (const float*)d_in[5];
    const float* fW        = (const float*)d_in[6];
    const float* fb        = (const float*)d_in[7];
    const float* eW        = (const float*)d_in[8];
    const float* eb        = (const float*)d_in[9];
    const float* aW        = (const float*)d_in[10];
    const float* ab        = (const float*)d_in[11];
    const float* pW        = (const float*)d_in[12];
    const float* pb        = (const float*)d_in[13];
    float* out = (float*)d_out;

    k_pre <<<750, 256>>>(skills, responses, k_emb, v_emb, Mk, fW, fb, eW, eb, aW, ab);
    k_scan<<<512, 256>>>(Mv0);
    k_out <<<398, 256>>>(fW, pW, pb, out);
}

// round 13
// speedup vs baseline: 1.8482x; 1.0007x over previous
#include <cuda_runtime.h>

#define BB 64
#define TT 200
#define NS 1000

typedef unsigned long long u64;

// ---------------- device scratch ----------------
__device__ __align__(16) float2 g_Wsk[1000 * 32]; // (w[l], w[l+32]) per skill
__device__ __align__(16) float2 g_EA [2000 * 64]; // (e, a) per x-index, per d
__device__ __align__(16) float2 g_G  [1000 * 32]; // k·fW2^T + fb
__device__ int    g_idx[BB * TT];                 // skill | (x << 16)
__device__ __align__(16) float  g_read[BB * TT * 64];

static __device__ __forceinline__ float tanh_a(float x) {
    float y; asm("tanh.approx.f32 %0, %1;" : "=f"(y) : "f"(x)); return y;
}
static __device__ __forceinline__ float sigmoid_e(float x) {
    return 1.0f / (1.0f + __expf(-x));
}
static __device__ __forceinline__ u64 pack2(float lo, float hi) {
    u64 r; asm("mov.b64 %0, {%1, %2};" : "=l"(r) : "f"(lo), "f"(hi)); return r;
}
static __device__ __forceinline__ u64 fma2(u64 a, u64 b, u64 c) {
    u64 d; asm("fma.rn.f32x2 %0, %1, %2, %3;" : "=l"(d) : "l"(a), "l"(b), "l"(c)); return d;
}
static __device__ __forceinline__ u64 mul2(u64 a, u64 b) {
    u64 d; asm("mul.rn.f32x2 %0, %1, %2;" : "=l"(d) : "l"(a), "l"(b)); return d;
}

// =====================================================================
// Kernel P: precompute tables (R12 warp-pair version, unchanged).
// =====================================================================
__global__ __launch_bounds__(256) void k_pre(
    const int* __restrict__ skills, const int* __restrict__ responses,
    const float* __restrict__ k_emb, const float* __restrict__ v_emb,
    const float* __restrict__ Mk, const float* __restrict__ fW,
    const float* __restrict__ fb, const float* __restrict__ eW,
    const float* __restrict__ eb, const float* __restrict__ aW,
    const float* __restrict__ ab)
{
    __shared__ __align__(16) float W0[64 * 68];
    __shared__ __align__(16) float W1[64 * 68];
    __shared__ __align__(16) float xch[4][64];

    int tid = threadIdx.x;
    int w = tid >> 5, l = tid & 31;
    int pair = w >> 1;
    int mat  = w & 1;
    bool isA = blockIdx.x < 250;
    int row = isA ? (blockIdx.x * 4 + pair) : ((blockIdx.x - 250) * 4 + pair);

    const float4* xp = isA ? (const float4*)&k_emb[row * 64]
                           : (const float4*)&v_emb[row * 64];
    float4 xr[16];
#pragma unroll
    for (int q = 0; q < 16; q++) xr[q] = xp[q];

    int gt = blockIdx.x * 256 + tid;
    if (gt < BB * TT) {
        int s = skills[gt], r = responses[gt];
        int mr = (r > -1) ? r : 0;
        g_idx[gt] = s | ((s + NS * mr) << 16);
    }

    {
        const float4* s0 = isA ? (const float4*)Mk : (const float4*)eW;
        const float4* s1f = (const float4*)fW;
        const float4* s1a = (const float4*)aW;
        float4 v0[4], v1[4];
#pragma unroll
        for (int k = 0; k < 4; k++) {
            int i = tid + k * 256;
            int o = i >> 4, q4 = i & 15;
            v0[k] = s0[i];
            v1[k] = isA ? s1f[o * 32 + 16 + q4] : s1a[i];
        }
#pragma unroll
        for (int k = 0; k < 4; k++) {
            int i = tid + k * 256;
            int o = i >> 4, q4 = i & 15;
            *(float4*)&W0[o * 68 + q4 * 4] = v0[k];
            *(float4*)&W1[o * 68 + q4 * 4] = v1[k];
        }
    }
    __syncthreads();

    const float* Wm = mat ? W1 : W0;
    const float4* pL = (const float4*)&Wm[l * 68];
    const float4* pH = (const float4*)&Wm[(l + 32) * 68];

    float cLa = 0.f, cLb = 0.f, cHa = 0.f, cHb = 0.f;
#pragma unroll
    for (int q = 0; q < 16; q += 2) {
        float4 xa = xr[q];
        float4 xb = xr[q + 1];
        float4 mLa = pL[q]; float4 mLb = pL[q + 1];
        float4 mHa = pH[q]; float4 mHb = pH[q + 1];
        cLa = fmaf(xa.x, mLa.x, cLa); cLa = fmaf(xa.y, mLa.y, cLa);
        cLa = fmaf(xa.z, mLa.z, cLa); cLa = fmaf(xa.w, mLa.w, cLa);
        cHa = fmaf(xa.x, mHa.x, cHa); cHa = fmaf(xa.y, mHa.y, cHa);
        cHa = fmaf(xa.z, mHa.z, cHa); cHa = fmaf(xa.w, mHa.w, cHa);
        cLb = fmaf(xb.x, mLb.x, cLb); cLb = fmaf(xb.y, mLb.y, cLb);
        cLb = fmaf(xb.z, mLb.z, cLb); cLb = fmaf(xb.w, mLb.w, cLb);
        cHb = fmaf(xb.x, mHb.x, cHb); cHb = fmaf(xb.y, mHb.y, cHb);
        cHb = fmaf(xb.z, mHb.z, cHb); cHb = fmaf(xb.w, mHb.w, cHb);
    }
    float cl = cLa + cLb, ch = cHa + cHb;

    if (isA) {
        if (mat == 0) {
            float e0 = __expf(cl), e1 = __expf(ch);
            float s = e0 + e1;
#pragma unroll
            for (int o = 16; o; o >>= 1) s += __shfl_xor_sync(~0u, s, o);
            float inv = 1.0f / s;
            g_Wsk[row * 32 + l] = make_float2(e0 * inv, e1 * inv);
        } else {
            g_G[row * 32 + l] = make_float2(cl + fb[l], ch + fb[l + 32]);
        }
    } else {
        if (mat == 1) {
            xch[pair][l]      = tanhf(cl + ab[l]);
            xch[pair][l + 32] = tanhf(ch + ab[l + 32]);
        }
        __syncthreads();
        if (mat == 0) {
            g_EA[row * 64 + l]      = make_float2(sigmoid_e(cl + eb[l]),      xch[pair][l]);
            g_EA[row * 64 + l + 32] = make_float2(sigmoid_e(ch + eb[l + 32]), xch[pair][l + 32]);
        }
    }
}

// =====================================================================
// Kernel S: scan, 2 d's per warp, packed f32x2 math. 512 blocks x 128thr
// (2048 warps); block = 4 warps of one batch covering 8 d's.
// Register-pipelined double-buffered staging; LDS-only inner loop.
// =====================================================================
__global__ __launch_bounds__(128) void k_scan(const float* __restrict__ Mv0)
{
    __shared__ __align__(16) float2 w_s[2][32][32];   // 16KB  (step, lane)->(w[l],w[l+32])
    __shared__ __align__(16) float4 ea_s[2][32][4];   //  4KB  (step, dpair)->(-e0,-e1,a0,a1)
    __shared__ __align__(16) float2 buf[4][8][38];    // 9.5KB deferred reads (r_d0,r_d1)

    int tid = threadIdx.x;
    int w = tid >> 5, l = tid & 31;
    int b = blockIdx.x >> 3;
    int dbase = (blockIdx.x & 7) << 3;
    int d0 = dbase + 2 * w;

    float2 m0 = *(const float2*)&Mv0[l * 64 + d0];
    float2 m1 = *(const float2*)&Mv0[(l + 32) * 64 + d0];
    u64 sa = pack2(m0.x, m0.y);      // state (d0,d1) for m=l
    u64 sb = pack2(m1.x, m1.y);      // state (d0,d1) for m=l+32

    const int* idxp = g_idx + b * TT;
    float* rd = g_read + b * TT * 64 + d0;
    float2 (*mybuf)[38] = buf[w];

    int est = tid >> 2, edp = tid & 3;   // ea staging: step 0..31, dpair 0..3
    int dhalf = (dbase >> 1);

    float2 wv[8]; float4 eav;
    // ---- stage chunk 0 into buffer 0
#pragma unroll
    for (int k = 0; k < 8; k++) {
        int p = idxp[w + 4 * k];
        wv[k] = g_Wsk[(p & 0xffff) * 32 + l];
    }
    {
        int pe = idxp[est];
        float4 v = ((const float4*)g_EA)[(pe >> 16) * 32 + dhalf + edp]; // (e0,a0,e1,a1)
        eav = make_float4(-v.x, -v.z, v.y, v.w);
    }
#pragma unroll
    for (int k = 0; k < 8; k++) w_s[0][w + 4 * k][l] = wv[k];
    ea_s[0][est][edp] = eav;
    __syncthreads();

    for (int c = 0; c < 6; c++) {
        int cur = c & 1;
        // ---- stage chunk c+1 into registers (tail clamped)
        if (c < 5) {
            int t0n = (c + 1) * 32;
#pragma unroll
            for (int k = 0; k < 8; k++) {
                int p = idxp[t0n + w + 4 * k];
                wv[k] = g_Wsk[(p & 0xffff) * 32 + l];
            }
            int pe = idxp[t0n + est];
            float4 v = ((const float4*)g_EA)[(pe >> 16) * 32 + dhalf + edp];
            eav = make_float4(-v.x, -v.z, v.y, v.w);
        } else {
#pragma unroll
            for (int k = 0; k < 8; k++) {
                int st = w + 4 * k; st = st < 8 ? st : 7;
                int p = idxp[192 + st];
                wv[k] = g_Wsk[(p & 0xffff) * 32 + l];
            }
            int st2 = est < 8 ? est : 7;
            int pe = idxp[192 + st2];
            float4 v = ((const float4*)g_EA)[(pe >> 16) * 32 + dhalf + edp];
            eav = make_float4(-v.x, -v.z, v.y, v.w);
        }

        // ---- compute chunk c (LDS-only, packed f32x2)
        int t0 = c * 32;
#pragma unroll
        for (int h = 0; h < 4; h++) {
#pragma unroll
            for (int j = 0; j < 8; j++) {
                int t = h * 8 + j;
                float2 w2 = w_s[cur][t][l];
                float4 ea = ea_s[cur][t][w];
                u64 wx2 = pack2(w2.x, w2.x);
                u64 wy2 = pack2(w2.y, w2.y);
                u64 ne2 = pack2(ea.x, ea.y);     // (-e0,-e1)
                u64 a2  = pack2(ea.z, ea.w);     // ( a0, a1)
                u64 r2  = mul2(wx2, sa);         // read BEFORE update
                r2 = fma2(wy2, sb, r2);
                u64 ia = fma2(ne2, sa, a2);
                u64 ib = fma2(ne2, sb, a2);
                sa = fma2(wx2, ia, sa);
                sb = fma2(wy2, ib, sb);
                *(u64*)&mybuf[j][l] = r2;
            }
            __syncwarp();
            if (l < 8) {
                const float4* rowp = (const float4*)&mybuf[l][0];
                float s0r = 0.f, s1r = 0.f;
#pragma unroll
                for (int k = 0; k < 16; k++) {
                    float4 v = rowp[k];
                    s0r += v.x + v.z;
                    s1r += v.y + v.w;
                }
                *(float2*)&rd[(t0 + h * 8 + l) * 64] = make_float2(s0r, s1r);
            }
            __syncwarp();
        }

        // ---- commit staged registers into the other buffer
        int nb = cur ^ 1;
#pragma unroll
        for (int k = 0; k < 8; k++) w_s[nb][w + 4 * k][l] = wv[k];
        ea_s[nb][est][edp] = eav;
        __syncthreads();
    }

    // ---- tail: 8 steps from buffer 0
    {
#pragma unroll
        for (int j = 0; j < 8; j++) {
            float2 w2 = w_s[0][j][l];
            float4 ea = ea_s[0][j][w];
            u64 wx2 = pack2(w2.x, w2.x);
            u64 wy2 = pack2(w2.y, w2.y);
            u64 ne2 = pack2(ea.x, ea.y);
            u64 a2  = pack2(ea.z, ea.w);
            u64 r2  = mul2(wx2, sa);
            r2 = fma2(wy2, sb, r2);
            u64 ia = fma2(ne2, sa, a2);
            u64 ib = fma2(ne2, sb, a2);
            sa = fma2(wx2, ia, sa);
            sb = fma2(wy2, ib, sb);
            *(u64*)&mybuf[j][l] = r2;
        }
        __syncwarp();
        if (l < 8) {
            const float4* rowp = (const float4*)&mybuf[l][0];
            float s0r = 0.f, s1r = 0.f;
#pragma unroll
            for (int k = 0; k < 16; k++) {
                float4 v = rowp[k];
                s0r += v.x + v.z;
                s1r += v.y + v.w;
            }
            *(float2*)&rd[(192 + l) * 64] = make_float2(s0r, s1r);
        }
    }
}

// =====================================================================
// Kernel O: p = sigmoid( tanh(read·fW1^T + G[skill]) · pW^T + pb )
// (R8 version verbatim)
// =====================================================================
__global__ __launch_bounds__(256, 5) void k_out(
    const float* __restrict__ fW, const float* __restrict__ pW,
    const float* __restrict__ pb, float* __restrict__ out)
{
    __shared__ __align__(16) float F1[64 * 68];
    __shared__ __align__(16) float x_s[8][2][64];

    int tid = threadIdx.x;
    {
        const float4* src = (const float4*)fW;
#pragma unroll
        for (int k = 0; k < 4; k++) {
            int i = tid + k * 256;
            int o = i >> 4, q4 = i & 15;
            *(float4*)&F1[o * 68 + q4 * 4] = src[o * 32 + q4];
        }
    }
    __syncthreads();

    int w = tid >> 5, l = tid & 31;
    const float4* pL = (const float4*)&F1[l * 68];
    const float4* pH = (const float4*)&F1[(l + 32) * 68];
    float pl = pW[l], ph = pW[l + 32];
    float pbv = pb[0];

    for (int rp = 0; rp < 2; rp++) {
        int row0 = blockIdx.x * 32 + w * 4 + rp * 2;
        int row1 = row0 + 1;
        int b0 = row0 / 199, t0 = row0 - b0 * 199 + 1;
        int b1 = row1 / 199, t1 = row1 - b1 * 199 + 1;
        int i0 = b0 * TT + t0, i1 = b1 * TT + t1;

        *(float2*)&x_s[w][0][2 * l] = ((const float2*)&g_read[i0 * 64])[l];
        *(float2*)&x_s[w][1][2 * l] = ((const float2*)&g_read[i1 * 64])[l];
        __syncwarp();

        float a00 = 0.f, a01 = 0.f, a10 = 0.f, a11 = 0.f;
#pragma unroll
        for (int q = 0; q < 16; q++) {
            float4 xa = *(const float4*)&x_s[w][0][q * 4];
            float4 xb = *(const float4*)&x_s[w][1][q * 4];
            float4 mL = pL[q];
            float4 mH = pH[q];
            a00 = fmaf(xa.x, mL.x, a00); a00 = fmaf(xa.y, mL.y, a00);
            a00 = fmaf(xa.z, mL.z, a00); a00 = fmaf(xa.w, mL.w, a00);
            a01 = fmaf(xa.x, mH.x, a01); a01 = fmaf(xa.y, mH.y, a01);
            a01 = fmaf(xa.z, mH.z, a01); a01 = fmaf(xa.w, mH.w, a01);
            a10 = fmaf(xb.x, mL.x, a10); a10 = fmaf(xb.y, mL.y, a10);
            a10 = fmaf(xb.z, mL.z, a10); a10 = fmaf(xb.w, mL.w, a10);
            a11 = fmaf(xb.x, mH.x, a11); a11 = fmaf(xb.y, mH.y, a11);
            a11 = fmaf(xb.z, mH.z, a11); a11 = fmaf(xb.w, mH.w, a11);
        }

        int sk0 = g_idx[i0] & 0xffff;
        int sk1 = g_idx[i1] & 0xffff;
        float2 G0 = g_G[sk0 * 32 + l];
        float2 G1 = g_G[sk1 * 32 + l];

        float f00 = tanh_a(a00 + G0.x), f01 = tanh_a(a01 + G0.y);
        float f10 = tanh_a(a10 + G1.x), f11 = tanh_a(a11 + G1.y);

        float r0 = f00 * pl + f01 * ph;
        float r1 = f10 * pl + f11 * ph;
#pragma unroll
        for (int o = 16; o; o >>= 1) {
            r0 += __shfl_xor_sync(~0u, r0, o);
            r1 += __shfl_xor_sync(~0u, r1, o);
        }
        if (l == 0) {
            out[row0] = sigmoid_e(r0 + pbv);
            out[row1] = sigmoid_e(r1 + pbv);
        }
        __syncwarp();
    }
}

// =====================================================================
// launch
// =====================================================================
extern "C" void kernel_launch(void* const* d_in, const int* in_sizes, int n_in,
                              void* d_out, int out_size) {
    const int*   skills    = (const int*)d_in[0];
    const int*   responses = (const int*)d_in[1];
    const float* k_emb     = (const float*)d_in[2];
    const float* v_emb     = (const float*)d_in[3];
    const float* Mk        = (const float*)d_in[4];
    const float* Mv0       = (const float*)d_in[5];
    const float* fW        = (const float*)d_in[6];
    const float* fb        = (const float*)d_in[7];
    const float* eW        = (const float*)d_in[8];
    const float* eb        = (const float*)d_in[9];
    const float* aW        = (const float*)d_in[10];
    const float* ab        = (const float*)d_in[11];
    const float* pW        = (const float*)d_in[12];
    const float* pb        = (const float*)d_in[13];
    float* out = (float*)d_out;

    k_pre <<<750, 256>>>(skills, responses, k_emb, v_emb, Mk, fW, fb, eW, eb, aW, ab);
    k_scan<<<512, 128>>>(Mv0);
    k_out <<<398, 256>>>(fW, pW, pb, out);
}

// round 14
// speedup vs baseline: 1.9239x; 1.0410x over previous
#include <cuda_runtime.h>

#define BB 64
#define TT 200
#define NS 1000

typedef unsigned long long u64;

// ---------------- device scratch ----------------
__device__ __align__(16) float2 g_Wsk[1000 * 32]; // (w[l], w[l+32]) per skill
__device__ __align__(16) float2 g_EA [2000 * 64]; // (e, a) per x-index, per d
__device__ __align__(16) float2 g_G  [1000 * 32]; // k·fW2^T + fb
__device__ int    g_idx[BB * TT];                 // skill | (x << 16)
__device__ __align__(16) float  g_read[BB * TT * 64];

static __device__ __forceinline__ float tanh_a(float x) {
    float y; asm("tanh.approx.f32 %0, %1;" : "=f"(y) : "f"(x)); return y;
}
static __device__ __forceinline__ float sigmoid_e(float x) {
    return 1.0f / (1.0f + __expf(-x));
}
static __device__ __forceinline__ u64 pack2(float lo, float hi) {
    u64 r; asm("mov.b64 %0, {%1, %2};" : "=l"(r) : "f"(lo), "f"(hi)); return r;
}
static __device__ __forceinline__ u64 fma2(u64 a, u64 b, u64 c) {
    u64 d; asm("fma.rn.f32x2 %0, %1, %2, %3;" : "=l"(d) : "l"(a), "l"(b), "l"(c)); return d;
}
static __device__ __forceinline__ u64 mul2(u64 a, u64 b) {
    u64 d; asm("mul.rn.f32x2 %0, %1, %2;" : "=l"(d) : "l"(a), "l"(b)); return d;
}

// =====================================================================
// Kernel P: precompute tables. Warp = (row-pair, matrix): 2 rows per
// warp amortize the weight-row smem reads; x vectors broadcast from smem.
//   blocks [0,125):   skill rows (8/block): Wsk (mat0), G (mat1)
//   blocks [125,375): x rows (8/block):     EA (mat0=e, mat1=a)
// =====================================================================
__global__ __launch_bounds__(256) void k_pre(
    const int* __restrict__ skills, const int* __restrict__ responses,
    const float* __restrict__ k_emb, const float* __restrict__ v_emb,
    const float* __restrict__ Mk, const float* __restrict__ fW,
    const float* __restrict__ fb, const float* __restrict__ eW,
    const float* __restrict__ eb, const float* __restrict__ aW,
    const float* __restrict__ ab)
{
    __shared__ __align__(16) float W0[64 * 68];
    __shared__ __align__(16) float W1[64 * 68];
    __shared__ __align__(16) float x_s[8][64];
    __shared__ __align__(16) float xch[8][64];

    int tid = threadIdx.x;
    int w = tid >> 5, l = tid & 31;
    int pair = w >> 1;            // 0..3 -> rows 2*pair, 2*pair+1 (block-local)
    int mat  = w & 1;             // 0 -> W0, 1 -> W1
    bool isA = blockIdx.x < 125;
    int rbase = isA ? (blockIdx.x * 8) : ((blockIdx.x - 125) * 8);

    // 1) g_idx
    int gt = blockIdx.x * 256 + tid;
    if (gt < BB * TT) {
        int s = skills[gt], r = responses[gt];
        int mr = (r > -1) ? r : 0;
        g_idx[gt] = s | ((s + NS * mr) << 16);
    }

    // 2) stage 8 x rows (coalesced; rows are sequential)
    if (tid < 128) {
        const float4* src = isA ? (const float4*)&k_emb[rbase * 64]
                                : (const float4*)&v_emb[rbase * 64];
        ((float4*)x_s)[tid] = src[tid];
    }

    // 3) stage both weight matrices
    {
        const float4* s0 = isA ? (const float4*)Mk : (const float4*)eW;
        const float4* s1f = (const float4*)fW;
        const float4* s1a = (const float4*)aW;
        float4 v0[4], v1[4];
#pragma unroll
        for (int k = 0; k < 4; k++) {
            int i = tid + k * 256;
            int o = i >> 4, q4 = i & 15;
            v0[k] = s0[i];
            v1[k] = isA ? s1f[o * 32 + 16 + q4] : s1a[i];
        }
#pragma unroll
        for (int k = 0; k < 4; k++) {
            int i = tid + k * 256;
            int o = i >> 4, q4 = i & 15;
            *(float4*)&W0[o * 68 + q4 * 4] = v0[k];
            *(float4*)&W1[o * 68 + q4 * 4] = v1[k];
        }
    }
    __syncthreads();

    // 4) GEMV: 2 rows x 1 matrix per warp; outputs (l, l+32) per row
    const float* Wm = mat ? W1 : W0;
    const float4* pL = (const float4*)&Wm[l * 68];
    const float4* pH = (const float4*)&Wm[(l + 32) * 68];
    const float4* xs0 = (const float4*)&x_s[pair * 2][0];
    const float4* xs1 = (const float4*)&x_s[pair * 2 + 1][0];

    float c0L = 0.f, c0H = 0.f, c1L = 0.f, c1H = 0.f;
    float d0L = 0.f, d0H = 0.f, d1L = 0.f, d1H = 0.f;
#pragma unroll
    for (int q = 0; q < 16; q += 2) {
        float4 xa0 = xs0[q];     float4 xb0 = xs0[q + 1];
        float4 xa1 = xs1[q];     float4 xb1 = xs1[q + 1];
        float4 mLa = pL[q];      float4 mLb = pL[q + 1];
        float4 mHa = pH[q];      float4 mHb = pH[q + 1];
        c0L = fmaf(xa0.x, mLa.x, c0L); c0L = fmaf(xa0.y, mLa.y, c0L);
        c0L = fmaf(xa0.z, mLa.z, c0L); c0L = fmaf(xa0.w, mLa.w, c0L);
        c0H = fmaf(xa0.x, mHa.x, c0H); c0H = fmaf(xa0.y, mHa.y, c0H);
        c0H = fmaf(xa0.z, mHa.z, c0H); c0H = fmaf(xa0.w, mHa.w, c0H);
        c1L = fmaf(xa1.x, mLa.x, c1L); c1L = fmaf(xa1.y, mLa.y, c1L);
        c1L = fmaf(xa1.z, mLa.z, c1L); c1L = fmaf(xa1.w, mLa.w, c1L);
        c1H = fmaf(xa1.x, mHa.x, c1H); c1H = fmaf(xa1.y, mHa.y, c1H);
        c1H = fmaf(xa1.z, mHa.z, c1H); c1H = fmaf(xa1.w, mHa.w, c1H);
        d0L = fmaf(xb0.x, mLb.x, d0L); d0L = fmaf(xb0.y, mLb.y, d0L);
        d0L = fmaf(xb0.z, mLb.z, d0L); d0L = fmaf(xb0.w, mLb.w, d0L);
        d0H = fmaf(xb0.x, mHb.x, d0H); d0H = fmaf(xb0.y, mHb.y, d0H);
        d0H = fmaf(xb0.z, mHb.z, d0H); d0H = fmaf(xb0.w, mHb.w, d0H);
        d1L = fmaf(xb1.x, mLb.x, d1L); d1L = fmaf(xb1.y, mLb.y, d1L);
        d1L = fmaf(xb1.z, mLb.z, d1L); d1L = fmaf(xb1.w, mLb.w, d1L);
        d1H = fmaf(xb1.x, mHb.x, d1H); d1H = fmaf(xb1.y, mHb.y, d1H);
        d1H = fmaf(xb1.z, mHb.z, d1H); d1H = fmaf(xb1.w, mHb.w, d1H);
    }
    float r0L = c0L + d0L, r0H = c0H + d0H;   // row 2*pair
    float r1L = c1L + d1L, r1H = c1H + d1H;   // row 2*pair+1

    int row0 = rbase + pair * 2;
    int row1 = row0 + 1;

    if (isA) {
        if (mat == 0) {
            // softmax over 64 logits per row (tiny logits; skip max-sub)
            float e00 = __expf(r0L), e01 = __expf(r0H);
            float e10 = __expf(r1L), e11 = __expf(r1H);
            float s0 = e00 + e01, s1 = e10 + e11;
#pragma unroll
            for (int o = 16; o; o >>= 1) {
                s0 += __shfl_xor_sync(~0u, s0, o);
                s1 += __shfl_xor_sync(~0u, s1, o);
            }
            float i0 = 1.0f / s0, i1 = 1.0f / s1;
            g_Wsk[row0 * 32 + l] = make_float2(e00 * i0, e01 * i0);
            g_Wsk[row1 * 32 + l] = make_float2(e10 * i1, e11 * i1);
        } else {
            float fbl = fb[l], fbh = fb[l + 32];
            g_G[row0 * 32 + l] = make_float2(r0L + fbl, r0H + fbh);
            g_G[row1 * 32 + l] = make_float2(r1L + fbl, r1H + fbh);
        }
    } else {
        int p0 = pair * 2, p1 = pair * 2 + 1;
        if (mat == 1) {
            float abl = ab[l], abh = ab[l + 32];
            xch[p0][l]      = tanhf(r0L + abl);
            xch[p0][l + 32] = tanhf(r0H + abh);
            xch[p1][l]      = tanhf(r1L + abl);
            xch[p1][l + 32] = tanhf(r1H + abh);
        }
        __syncthreads();
        if (mat == 0) {
            float ebl = eb[l], ebh = eb[l + 32];
            g_EA[row0 * 64 + l]      = make_float2(sigmoid_e(r0L + ebl), xch[p0][l]);
            g_EA[row0 * 64 + l + 32] = make_float2(sigmoid_e(r0H + ebh), xch[p0][l + 32]);
            g_EA[row1 * 64 + l]      = make_float2(sigmoid_e(r1L + ebl), xch[p1][l]);
            g_EA[row1 * 64 + l + 32] = make_float2(sigmoid_e(r1H + ebh), xch[p1][l + 32]);
        }
    }
}

// =====================================================================
// Kernel S: scan (R13 version verbatim): 2 d's per warp, f32x2 math,
// register-pipelined double-buffered staging, LDS-only inner loop.
// =====================================================================
__global__ __launch_bounds__(128) void k_scan(const float* __restrict__ Mv0)
{
    __shared__ __align__(16) float2 w_s[2][32][32];   // 16KB
    __shared__ __align__(16) float4 ea_s[2][32][4];   //  4KB
    __shared__ __align__(16) float2 buf[4][8][38];    // 9.5KB

    int tid = threadIdx.x;
    int w = tid >> 5, l = tid & 31;
    int b = blockIdx.x >> 3;
    int dbase = (blockIdx.x & 7) << 3;
    int d0 = dbase + 2 * w;

    float2 m0 = *(const float2*)&Mv0[l * 64 + d0];
    float2 m1 = *(const float2*)&Mv0[(l + 32) * 64 + d0];
    u64 sa = pack2(m0.x, m0.y);
    u64 sb = pack2(m1.x, m1.y);

    const int* idxp = g_idx + b * TT;
    float* rd = g_read + b * TT * 64 + d0;
    float2 (*mybuf)[38] = buf[w];

    int est = tid >> 2, edp = tid & 3;
    int dhalf = (dbase >> 1);

    float2 wv[8]; float4 eav;
#pragma unroll
    for (int k = 0; k < 8; k++) {
        int p = idxp[w + 4 * k];
        wv[k] = g_Wsk[(p & 0xffff) * 32 + l];
    }
    {
        int pe = idxp[est];
        float4 v = ((const float4*)g_EA)[(pe >> 16) * 32 + dhalf + edp];
        eav = make_float4(-v.x, -v.z, v.y, v.w);
    }
#pragma unroll
    for (int k = 0; k < 8; k++) w_s[0][w + 4 * k][l] = wv[k];
    ea_s[0][est][edp] = eav;
    __syncthreads();

    for (int c = 0; c < 6; c++) {
        int cur = c & 1;
        if (c < 5) {
            int t0n = (c + 1) * 32;
#pragma unroll
            for (int k = 0; k < 8; k++) {
                int p = idxp[t0n + w + 4 * k];
                wv[k] = g_Wsk[(p & 0xffff) * 32 + l];
            }
            int pe = idxp[t0n + est];
            float4 v = ((const float4*)g_EA)[(pe >> 16) * 32 + dhalf + edp];
            eav = make_float4(-v.x, -v.z, v.y, v.w);
        } else {
#pragma unroll
            for (int k = 0; k < 8; k++) {
                int st = w + 4 * k; st = st < 8 ? st : 7;
                int p = idxp[192 + st];
                wv[k] = g_Wsk[(p & 0xffff) * 32 + l];
            }
            int st2 = est < 8 ? est : 7;
            int pe = idxp[192 + st2];
            float4 v = ((const float4*)g_EA)[(pe >> 16) * 32 + dhalf + edp];
            eav = make_float4(-v.x, -v.z, v.y, v.w);
        }

        int t0 = c * 32;
#pragma unroll
        for (int h = 0; h < 4; h++) {
#pragma unroll
            for (int j = 0; j < 8; j++) {
                int t = h * 8 + j;
                float2 w2 = w_s[cur][t][l];
                float4 ea = ea_s[cur][t][w];
                u64 wx2 = pack2(w2.x, w2.x);
                u64 wy2 = pack2(w2.y, w2.y);
                u64 ne2 = pack2(ea.x, ea.y);
                u64 a2  = pack2(ea.z, ea.w);
                u64 r2  = mul2(wx2, sa);
                r2 = fma2(wy2, sb, r2);
                u64 ia = fma2(ne2, sa, a2);
                u64 ib = fma2(ne2, sb, a2);
                sa = fma2(wx2, ia, sa);
                sb = fma2(wy2, ib, sb);
                *(u64*)&mybuf[j][l] = r2;
            }
            __syncwarp();
            if (l < 8) {
                const float4* rowp = (const float4*)&mybuf[l][0];
                float s0r = 0.f, s1r = 0.f;
#pragma unroll
                for (int k = 0; k < 16; k++) {
                    float4 v = rowp[k];
                    s0r += v.x + v.z;
                    s1r += v.y + v.w;
                }
                *(float2*)&rd[(t0 + h * 8 + l) * 64] = make_float2(s0r, s1r);
            }
            __syncwarp();
        }

        int nb = cur ^ 1;
#pragma unroll
        for (int k = 0; k < 8; k++) w_s[nb][w + 4 * k][l] = wv[k];
        ea_s[nb][est][edp] = eav;
        __syncthreads();
    }

    {
#pragma unroll
        for (int j = 0; j < 8; j++) {
            float2 w2 = w_s[0][j][l];
            float4 ea = ea_s[0][j][w];
            u64 wx2 = pack2(w2.x, w2.x);
            u64 wy2 = pack2(w2.y, w2.y);
            u64 ne2 = pack2(ea.x, ea.y);
            u64 a2  = pack2(ea.z, ea.w);
            u64 r2  = mul2(wx2, sa);
            r2 = fma2(wy2, sb, r2);
            u64 ia = fma2(ne2, sa, a2);
            u64 ib = fma2(ne2, sb, a2);
            sa = fma2(wx2, ia, sa);
            sb = fma2(wy2, ib, sb);
            *(u64*)&mybuf[j][l] = r2;
        }
        __syncwarp();
        if (l < 8) {
            const float4* rowp = (const float4*)&mybuf[l][0];
            float s0r = 0.f, s1r = 0.f;
#pragma unroll
            for (int k = 0; k < 16; k++) {
                float4 v = rowp[k];
                s0r += v.x + v.z;
                s1r += v.y + v.w;
            }
            *(float2*)&rd[(192 + l) * 64] = make_float2(s0r, s1r);
        }
    }
}

// =====================================================================
// Kernel O: p = sigmoid( tanh(read·fW1^T + G[skill]) · pW^T + pb )
// (R8 version verbatim)
// =====================================================================
__global__ __launch_bounds__(256, 5) void k_out(
    const float* __restrict__ fW, const float* __restrict__ pW,
    const float* __restrict__ pb, float* __restrict__ out)
{
    __shared__ __align__(16) float F1[64 * 68];
    __shared__ __align__(16) float x_s[8][2][64];

    int tid = threadIdx.x;
    {
        const float4* src = (const float4*)fW;
#pragma unroll
        for (int k = 0; k < 4; k++) {
            int i = tid + k * 256;
            int o = i >> 4, q4 = i & 15;
            *(float4*)&F1[o * 68 + q4 * 4] = src[o * 32 + q4];
        }
    }
    __syncthreads();

    int w = tid >> 5, l = tid & 31;
    const float4* pL = (const float4*)&F1[l * 68];
    const float4* pH = (const float4*)&F1[(l + 32) * 68];
    float pl = pW[l], ph = pW[l + 32];
    float pbv = pb[0];

    for (int rp = 0; rp < 2; rp++) {
        int row0 = blockIdx.x * 32 + w * 4 + rp * 2;
        int row1 = row0 + 1;
        int b0 = row0 / 199, t0 = row0 - b0 * 199 + 1;
        int b1 = row1 / 199, t1 = row1 - b1 * 199 + 1;
        int i0 = b0 * TT + t0, i1 = b1 * TT + t1;

        *(float2*)&x_s[w][0][2 * l] = ((const float2*)&g_read[i0 * 64])[l];
        *(float2*)&x_s[w][1][2 * l] = ((const float2*)&g_read[i1 * 64])[l];
        __syncwarp();

        float a00 = 0.f, a01 = 0.f, a10 = 0.f, a11 = 0.f;
#pragma unroll
        for (int q = 0; q < 16; q++) {
            float4 xa = *(const float4*)&x_s[w][0][q * 4];
            float4 xb = *(const float4*)&x_s[w][1][q * 4];
            float4 mL = pL[q];
            float4 mH = pH[q];
            a00 = fmaf(xa.x, mL.x, a00); a00 = fmaf(xa.y, mL.y, a00);
            a00 = fmaf(xa.z, mL.z, a00); a00 = fmaf(xa.w, mL.w, a00);
            a01 = fmaf(xa.x, mH.x, a01); a01 = fmaf(xa.y, mH.y, a01);
            a01 = fmaf(xa.z, mH.z, a01); a01 = fmaf(xa.w, mH.w, a01);
            a10 = fmaf(xb.x, mL.x, a10); a10 = fmaf(xb.y, mL.y, a10);
            a10 = fmaf(xb.z, mL.z, a10); a10 = fmaf(xb.w, mL.w, a10);
            a11 = fmaf(xb.x, mH.x, a11); a11 = fmaf(xb.y, mH.y, a11);
            a11 = fmaf(xb.z, mH.z, a11); a11 = fmaf(xb.w, mH.w, a11);
        }

        int sk0 = g_idx[i0] & 0xffff;
        int sk1 = g_idx[i1] & 0xffff;
        float2 G0 = g_G[sk0 * 32 + l];
        float2 G1 = g_G[sk1 * 32 + l];

        float f00 = tanh_a(a00 + G0.x), f01 = tanh_a(a01 + G0.y);
        float f10 = tanh_a(a10 + G1.x), f11 = tanh_a(a11 + G1.y);

        float r0 = f00 * pl + f01 * ph;
        float r1 = f10 * pl + f11 * ph;
#pragma unroll
        for (int o = 16; o; o >>= 1) {
            r0 += __shfl_xor_sync(~0u, r0, o);
            r1 += __shfl_xor_sync(~0u, r1, o);
        }
        if (l == 0) {
            out[row0] = sigmoid_e(r0 + pbv);
            out[row1] = sigmoid_e(r1 + pbv);
        }
        __syncwarp();
    }
}

// =====================================================================
// launch
// =====================================================================
extern "C" void kernel_launch(void* const* d_in, const int* in_sizes, int n_in,
                              void* d_out, int out_size) {
    const int*   skills    = (const int*)d_in[0];
    const int*   responses = (const int*)d_in[1];
    const float* k_emb     = (const float*)d_in[2];
    const float* v_emb     = (const float*)d_in[3];
    const float* Mk        = (const float*)d_in[4];
    const float* Mv0       = (const float*)d_in[5];
    const float* fW        = (const float*)d_in[6];
    const float* fb        = (const float*)d_in[7];
    const float* eW        = (const float*)d_in[8];
    const float* eb        = (const float*)d_in[9];
    const float* aW        = (const float*)d_in[10];
    const float* ab        = (const float*)d_in[11];
    const float* pW        = (const float*)d_in[12];
    const float* pb        = (const float*)d_in[13];
    float* out = (float*)d_out;

    k_pre <<<375, 256>>>(skills, responses, k_emb, v_emb, Mk, fW, fb, eW, eb, aW, ab);
    k_scan<<<512, 128>>>(Mv0);
    k_out <<<398, 256>>>(fW, pW, pb, out);
}

// round 16
// speedup vs baseline: 2.0293x; 1.0548x over previous
#include <cuda_runtime.h>

#define BB 64
#define TT 200
#define NS 1000

typedef unsigned long long u64;

// ---------------- device scratch ----------------
__device__ __align__(16) float2 g_Wsk[1000 * 32]; // (w[l], w[l+32]) per skill
__device__ __align__(16) float2 g_EA [2000 * 64]; // (e, a) per x-index, per d
__device__ __align__(16) float2 g_G  [1000 * 32]; // k·fW2^T + fb
__device__ int    g_idx[BB * TT];                 // skill | (x << 16)
__device__ __align__(16) float  g_read[BB * TT * 64];

static __device__ __forceinline__ float tanh_a(float x) {
    float y; asm("tanh.approx.f32 %0, %1;" : "=f"(y) : "f"(x)); return y;
}
static __device__ __forceinline__ float sigmoid_e(float x) {
    return 1.0f / (1.0f + __expf(-x));
}
static __device__ __forceinline__ u64 pack2(float lo, float hi) {
    u64 r; asm("mov.b64 %0, {%1, %2};" : "=l"(r) : "f"(lo), "f"(hi)); return r;
}
static __device__ __forceinline__ u64 fma2(u64 a, u64 b, u64 c) {
    u64 d; asm("fma.rn.f32x2 %0, %1, %2, %3;" : "=l"(d) : "l"(a), "l"(b), "l"(c)); return d;
}
static __device__ __forceinline__ u64 mul2(u64 a, u64 b) {
    u64 d; asm("mul.rn.f32x2 %0, %1, %2;" : "=l"(d) : "l"(a), "l"(b)); return d;
}

// =====================================================================
// Kernel P: precompute tables (R14 version verbatim, 8.5us).
// =====================================================================
__global__ __launch_bounds__(256) void k_pre(
    const int* __restrict__ skills, const int* __restrict__ responses,
    const float* __restrict__ k_emb, const float* __restrict__ v_emb,
    const float* __restrict__ Mk, const float* __restrict__ fW,
    const float* __restrict__ fb, const float* __restrict__ eW,
    const float* __restrict__ eb, const float* __restrict__ aW,
    const float* __restrict__ ab)
{
    __shared__ __align__(16) float W0[64 * 68];
    __shared__ __align__(16) float W1[64 * 68];
    __shared__ __align__(16) float x_s[8][64];
    __shared__ __align__(16) float xch[8][64];

    int tid = threadIdx.x;
    int w = tid >> 5, l = tid & 31;
    int pair = w >> 1;
    int mat  = w & 1;
    bool isA = blockIdx.x < 125;
    int rbase = isA ? (blockIdx.x * 8) : ((blockIdx.x - 125) * 8);

    int gt = blockIdx.x * 256 + tid;
    if (gt < BB * TT) {
        int s = skills[gt], r = responses[gt];
        int mr = (r > -1) ? r : 0;
        g_idx[gt] = s | ((s + NS * mr) << 16);
    }

    if (tid < 128) {
        const float4* src = isA ? (const float4*)&k_emb[rbase * 64]
                                : (const float4*)&v_emb[rbase * 64];
        ((float4*)x_s)[tid] = src[tid];
    }

    {
        const float4* s0 = isA ? (const float4*)Mk : (const float4*)eW;
        const float4* s1f = (const float4*)fW;
        const float4* s1a = (const float4*)aW;
        float4 v0[4], v1[4];
#pragma unroll
        for (int k = 0; k < 4; k++) {
            int i = tid + k * 256;
            int o = i >> 4, q4 = i & 15;
            v0[k] = s0[i];
            v1[k] = isA ? s1f[o * 32 + 16 + q4] : s1a[i];
        }
#pragma unroll
        for (int k = 0; k < 4; k++) {
            int i = tid + k * 256;
            int o = i >> 4, q4 = i & 15;
            *(float4*)&W0[o * 68 + q4 * 4] = v0[k];
            *(float4*)&W1[o * 68 + q4 * 4] = v1[k];
        }
    }
    __syncthreads();

    const float* Wm = mat ? W1 : W0;
    const float4* pL = (const float4*)&Wm[l * 68];
    const float4* pH = (const float4*)&Wm[(l + 32) * 68];
    const float4* xs0 = (const float4*)&x_s[pair * 2][0];
    const float4* xs1 = (const float4*)&x_s[pair * 2 + 1][0];

    float c0L = 0.f, c0H = 0.f, c1L = 0.f, c1H = 0.f;
    float d0L = 0.f, d0H = 0.f, d1L = 0.f, d1H = 0.f;
#pragma unroll
    for (int q = 0; q < 16; q += 2) {
        float4 xa0 = xs0[q];     float4 xb0 = xs0[q + 1];
        float4 xa1 = xs1[q];     float4 xb1 = xs1[q + 1];
        float4 mLa = pL[q];      float4 mLb = pL[q + 1];
        float4 mHa = pH[q];      float4 mHb = pH[q + 1];
        c0L = fmaf(xa0.x, mLa.x, c0L); c0L = fmaf(xa0.y, mLa.y, c0L);
        c0L = fmaf(xa0.z, mLa.z, c0L); c0L = fmaf(xa0.w, mLa.w, c0L);
        c0H = fmaf(xa0.x, mHa.x, c0H); c0H = fmaf(xa0.y, mHa.y, c0H);
        c0H = fmaf(xa0.z, mHa.z, c0H); c0H = fmaf(xa0.w, mHa.w, c0H);
        c1L = fmaf(xa1.x, mLa.x, c1L); c1L = fmaf(xa1.y, mLa.y, c1L);
        c1L = fmaf(xa1.z, mLa.z, c1L); c1L = fmaf(xa1.w, mLa.w, c1L);
        c1H = fmaf(xa1.x, mHa.x, c1H); c1H = fmaf(xa1.y, mHa.y, c1H);
        c1H = fmaf(xa1.z, mHa.z, c1H); c1H = fmaf(xa1.w, mHa.w, c1H);
        d0L = fmaf(xb0.x, mLb.x, d0L); d0L = fmaf(xb0.y, mLb.y, d0L);
        d0L = fmaf(xb0.z, mLb.z, d0L); d0L = fmaf(xb0.w, mLb.w, d0L);
        d0H = fmaf(xb0.x, mHb.x, d0H); d0H = fmaf(xb0.y, mHb.y, d0H);
        d0H = fmaf(xb0.z, mHb.z, d0H); d0H = fmaf(xb0.w, mHb.w, d0H);
        d1L = fmaf(xb1.x, mLb.x, d1L); d1L = fmaf(xb1.y, mLb.y, d1L);
        d1L = fmaf(xb1.z, mLb.z, d1L); d1L = fmaf(xb1.w, mLb.w, d1L);
        d1H = fmaf(xb1.x, mHb.x, d1H); d1H = fmaf(xb1.y, mHb.y, d1H);
        d1H = fmaf(xb1.z, mHb.z, d1H); d1H = fmaf(xb1.w, mHb.w, d1H);
    }
    float r0L = c0L + d0L, r0H = c0H + d0H;
    float r1L = c1L + d1L, r1H = c1H + d1H;

    int row0 = rbase + pair * 2;
    int row1 = row0 + 1;

    if (isA) {
        if (mat == 0) {
            float e00 = __expf(r0L), e01 = __expf(r0H);
            float e10 = __expf(r1L), e11 = __expf(r1H);
            float s0 = e00 + e01, s1 = e10 + e11;
#pragma unroll
            for (int o = 16; o; o >>= 1) {
                s0 += __shfl_xor_sync(~0u, s0, o);
                s1 += __shfl_xor_sync(~0u, s1, o);
            }
            float i0 = 1.0f / s0, i1 = 1.0f / s1;
            g_Wsk[row0 * 32 + l] = make_float2(e00 * i0, e01 * i0);
            g_Wsk[row1 * 32 + l] = make_float2(e10 * i1, e11 * i1);
        } else {
            float fbl = fb[l], fbh = fb[l + 32];
            g_G[row0 * 32 + l] = make_float2(r0L + fbl, r0H + fbh);
            g_G[row1 * 32 + l] = make_float2(r1L + fbl, r1H + fbh);
        }
    } else {
        int p0 = pair * 2, p1 = pair * 2 + 1;
        if (mat == 1) {
            float abl = ab[l], abh = ab[l + 32];
            xch[p0][l]      = tanhf(r0L + abl);
            xch[p0][l + 32] = tanhf(r0H + abh);
            xch[p1][l]      = tanhf(r1L + abl);
            xch[p1][l + 32] = tanhf(r1H + abh);
        }
        __syncthreads();
        if (mat == 0) {
            float ebl = eb[l], ebh = eb[l + 32];
            g_EA[row0 * 64 + l]      = make_float2(sigmoid_e(r0L + ebl), xch[p0][l]);
            g_EA[row0 * 64 + l + 32] = make_float2(sigmoid_e(r0H + ebh), xch[p0][l + 32]);
            g_EA[row1 * 64 + l]      = make_float2(sigmoid_e(r1L + ebl), xch[p1][l]);
            g_EA[row1 * 64 + l + 32] = make_float2(sigmoid_e(r1H + ebh), xch[p1][l + 32]);
        }
    }
}

// =====================================================================
// Kernel S: scan (R13 version verbatim): 2 d's per warp, f32x2 math,
// register-pipelined double-buffered staging, LDS-only inner loop.
// =====================================================================
__global__ __launch_bounds__(128) void k_scan(const float* __restrict__ Mv0)
{
    __shared__ __align__(16) float2 w_s[2][32][32];   // 16KB
    __shared__ __align__(16) float4 ea_s[2][32][4];   //  4KB
    __shared__ __align__(16) float2 buf[4][8][38];    // 9.5KB

    int tid = threadIdx.x;
    int w = tid >> 5, l = tid & 31;
    int b = blockIdx.x >> 3;
    int dbase = (blockIdx.x & 7) << 3;
    int d0 = dbase + 2 * w;

    float2 m0 = *(const float2*)&Mv0[l * 64 + d0];
    float2 m1 = *(const float2*)&Mv0[(l + 32) * 64 + d0];
    u64 sa = pack2(m0.x, m0.y);
    u64 sb = pack2(m1.x, m1.y);

    const int* idxp = g_idx + b * TT;
    float* rd = g_read + b * TT * 64 + d0;
    float2 (*mybuf)[38] = buf[w];

    int est = tid >> 2, edp = tid & 3;
    int dhalf = (dbase >> 1);

    float2 wv[8]; float4 eav;
#pragma unroll
    for (int k = 0; k < 8; k++) {
        int p = idxp[w + 4 * k];
        wv[k] = g_Wsk[(p & 0xffff) * 32 + l];
    }
    {
        int pe = idxp[est];
        float4 v = ((const float4*)g_EA)[(pe >> 16) * 32 + dhalf + edp];
        eav = make_float4(-v.x, -v.z, v.y, v.w);
    }
#pragma unroll
    for (int k = 0; k < 8; k++) w_s[0][w + 4 * k][l] = wv[k];
    ea_s[0][est][edp] = eav;
    __syncthreads();

    for (int c = 0; c < 6; c++) {
        int cur = c & 1;
        if (c < 5) {
            int t0n = (c + 1) * 32;
#pragma unroll
            for (int k = 0; k < 8; k++) {
                int p = idxp[t0n + w + 4 * k];
                wv[k] = g_Wsk[(p & 0xffff) * 32 + l];
            }
            int pe = idxp[t0n + est];
            float4 v = ((const float4*)g_EA)[(pe >> 16) * 32 + dhalf + edp];
            eav = make_float4(-v.x, -v.z, v.y, v.w);
        } else {
#pragma unroll
            for (int k = 0; k < 8; k++) {
                int st = w + 4 * k; st = st < 8 ? st : 7;
                int p = idxp[192 + st];
                wv[k] = g_Wsk[(p & 0xffff) * 32 + l];
            }
            int st2 = est < 8 ? est : 7;
            int pe = idxp[192 + st2];
            float4 v = ((const float4*)g_EA)[(pe >> 16) * 32 + dhalf + edp];
            eav = make_float4(-v.x, -v.z, v.y, v.w);
        }

        int t0 = c * 32;
#pragma unroll
        for (int h = 0; h < 4; h++) {
#pragma unroll
            for (int j = 0; j < 8; j++) {
                int t = h * 8 + j;
                float2 w2 = w_s[cur][t][l];
                float4 ea = ea_s[cur][t][w];
                u64 wx2 = pack2(w2.x, w2.x);
                u64 wy2 = pack2(w2.y, w2.y);
                u64 ne2 = pack2(ea.x, ea.y);
                u64 a2  = pack2(ea.z, ea.w);
                u64 r2  = mul2(wx2, sa);
                r2 = fma2(wy2, sb, r2);
                u64 ia = fma2(ne2, sa, a2);
                u64 ib = fma2(ne2, sb, a2);
                sa = fma2(wx2, ia, sa);
                sb = fma2(wy2, ib, sb);
                *(u64*)&mybuf[j][l] = r2;
            }
            __syncwarp();
            if (l < 8) {
                const float4* rowp = (const float4*)&mybuf[l][0];
                float s0r = 0.f, s1r = 0.f;
#pragma unroll
                for (int k = 0; k < 16; k++) {
                    float4 v = rowp[k];
                    s0r += v.x + v.z;
                    s1r += v.y + v.w;
                }
                *(float2*)&rd[(t0 + h * 8 + l) * 64] = make_float2(s0r, s1r);
            }
            __syncwarp();
        }

        int nb = cur ^ 1;
#pragma unroll
        for (int k = 0; k < 8; k++) w_s[nb][w + 4 * k][l] = wv[k];
        ea_s[nb][est][edp] = eav;
        __syncthreads();
    }

    {
#pragma unroll
        for (int j = 0; j < 8; j++) {
            float2 w2 = w_s[0][j][l];
            float4 ea = ea_s[0][j][w];
            u64 wx2 = pack2(w2.x, w2.x);
            u64 wy2 = pack2(w2.y, w2.y);
            u64 ne2 = pack2(ea.x, ea.y);
            u64 a2  = pack2(ea.z, ea.w);
            u64 r2  = mul2(wx2, sa);
            r2 = fma2(wy2, sb, r2);
            u64 ia = fma2(ne2, sa, a2);
            u64 ib = fma2(ne2, sb, a2);
            sa = fma2(wx2, ia, sa);
            sb = fma2(wy2, ib, sb);
            *(u64*)&mybuf[j][l] = r2;
        }
        __syncwarp();
        if (l < 8) {
            const float4* rowp = (const float4*)&mybuf[l][0];
            float s0r = 0.f, s1r = 0.f;
#pragma unroll
            for (int k = 0; k < 16; k++) {
                float4 v = rowp[k];
                s0r += v.x + v.z;
                s1r += v.y + v.w;
            }
            *(float2*)&rd[(192 + l) * 64] = make_float2(s0r, s1r);
        }
    }
}

// =====================================================================
// Kernel O: 4 rows per warp in ONE q-loop (weight reads amortized 4x).
// p = sigmoid( tanh(read·fW1^T + G[skill]) · pW^T + pb )
// =====================================================================
__global__ __launch_bounds__(256, 5) void k_out(
    const float* __restrict__ fW, const float* __restrict__ pW,
    const float* __restrict__ pb, float* __restrict__ out)
{
    __shared__ __align__(16) float F1[64 * 68];
    __shared__ __align__(16) float x_s[8][4][64];

    int tid = threadIdx.x;
    {
        const float4* src = (const float4*)fW;
#pragma unroll
        for (int k = 0; k < 4; k++) {
            int i = tid + k * 256;
            int o = i >> 4, q4 = i & 15;
            *(float4*)&F1[o * 68 + q4 * 4] = src[o * 32 + q4];
        }
    }
    __syncthreads();

    int w = tid >> 5, l = tid & 31;
    const float4* pL = (const float4*)&F1[l * 68];
    const float4* pH = (const float4*)&F1[(l + 32) * 68];
    float pl = pW[l], ph = pW[l + 32];
    float pbv = pb[0];

    int rowb = blockIdx.x * 32 + w * 4;
    int iidx[4];
#pragma unroll
    for (int r = 0; r < 4; r++) {
        int row = rowb + r;
        int b0 = row / 199, t0 = row - b0 * 199 + 1;
        iidx[r] = b0 * TT + t0;
        *(float2*)&x_s[w][r][2 * l] = ((const float2*)&g_read[iidx[r] * 64])[l];
    }
    __syncwarp();

    float aL[4] = {0.f, 0.f, 0.f, 0.f};
    float aH[4] = {0.f, 0.f, 0.f, 0.f};
#pragma unroll
    for (int q = 0; q < 16; q++) {
        float4 mL = pL[q];
        float4 mH = pH[q];
#pragma unroll
        for (int r = 0; r < 4; r++) {
            float4 xa = *(const float4*)&x_s[w][r][q * 4];
            aL[r] = fmaf(xa.x, mL.x, aL[r]); aL[r] = fmaf(xa.y, mL.y, aL[r]);
            aL[r] = fmaf(xa.z, mL.z, aL[r]); aL[r] = fmaf(xa.w, mL.w, aL[r]);
            aH[r] = fmaf(xa.x, mH.x, aH[r]); aH[r] = fmaf(xa.y, mH.y, aH[r]);
            aH[r] = fmaf(xa.z, mH.z, aH[r]); aH[r] = fmaf(xa.w, mH.w, aH[r]);
        }
    }

    float rv[4];
#pragma unroll
    for (int r = 0; r < 4; r++) {
        int sk = g_idx[iidx[r]] & 0xffff;
        float2 G = g_G[sk * 32 + l];
        float fL = tanh_a(aL[r] + G.x);
        float fH = tanh_a(aH[r] + G.y);
        rv[r] = fL * pl + fH * ph;
    }
#pragma unroll
    for (int o = 16; o; o >>= 1) {
#pragma unroll
        for (int r = 0; r < 4; r++)
            rv[r] += __shfl_xor_sync(~0u, rv[r], o);
    }
    if (l == 0) {
#pragma unroll
        for (int r = 0; r < 4; r++)
            out[rowb + r] = sigmoid_e(rv[r] + pbv);
    }
}

// =====================================================================
// launch
// =====================================================================
extern "C" void kernel_launch(void* const* d_in, const int* in_sizes, int n_in,
                              void* d_out, int out_size) {
    const int*   skills    = (const int*)d_in[0];
    const int*   responses = (const int*)d_in[1];
    const float* k_emb     = (const float*)d_in[2];
    const float* v_emb     = (const float*)d_in[3];
    const float* Mk        = (const float*)d_in[4];
    const float* Mv0       = (const float*)d_in[5];
    const float* fW        = (const float*)d_in[6];
    const float* fb        = (const float*)d_in[7];
    const float* eW        = (const float*)d_in[8];
    const float* eb        = (const float*)d_in[9];
    const float* aW        = (const float*)d_in[10];
    const float* ab        = (const float*)d_in[11];
    const float* pW        = (const float*)d_in[12];
    const float* pb        = (const float*)d_in[13];
    float* out = (float*)d_out;

    k_pre <<<375, 256>>>(skills, responses, k_emb, v_emb, Mk, fW, fb, eW, eb, aW, ab);
    k_scan<<<512, 128>>>(Mv0);
    k_out <<<398, 256>>>(fW, pW, pb, out);
}

// round 17
// speedup vs baseline: 2.8838x; 1.4211x over previous
#include <cuda_runtime.h>

#define BB 64
#define TT 200
#define NS 1000

// ---------------- device scratch ----------------
__device__ __align__(16) float  g_W  [1000 * 64]; // softmaxed w rows (plain layout)
__device__ __align__(16) float2 g_EA [2000 * 64]; // (e, a) per x-index, per d
__device__ __align__(16) float2 g_G  [1000 * 32]; // k·fW2^T + fb
__device__ int    g_idx[BB * TT];                 // skill | (x << 16)
__device__ __align__(16) float  g_read[BB * TT * 64];

static __device__ __forceinline__ float tanh_a(float x) {
    float y; asm("tanh.approx.f32 %0, %1;" : "=f"(y) : "f"(x)); return y;
}
static __device__ __forceinline__ float sigmoid_e(float x) {
    return 1.0f / (1.0f + __expf(-x));
}

// =====================================================================
// Kernel P: precompute tables (R14 structure; g_W layout plain rows).
// =====================================================================
__global__ __launch_bounds__(256) void k_pre(
    const int* __restrict__ skills, const int* __restrict__ responses,
    const float* __restrict__ k_emb, const float* __restrict__ v_emb,
    const float* __restrict__ Mk, const float* __restrict__ fW,
    const float* __restrict__ fb, const float* __restrict__ eW,
    const float* __restrict__ eb, const float* __restrict__ aW,
    const float* __restrict__ ab)
{
    __shared__ __align__(16) float W0[64 * 68];
    __shared__ __align__(16) float W1[64 * 68];
    __shared__ __align__(16) float x_s[8][64];
    __shared__ __align__(16) float xch[8][64];

    int tid = threadIdx.x;
    int w = tid >> 5, l = tid & 31;
    int pair = w >> 1;
    int mat  = w & 1;
    bool isA = blockIdx.x < 125;
    int rbase = isA ? (blockIdx.x * 8) : ((blockIdx.x - 125) * 8);

    int gt = blockIdx.x * 256 + tid;
    if (gt < BB * TT) {
        int s = skills[gt], r = responses[gt];
        int mr = (r > -1) ? r : 0;
        g_idx[gt] = s | ((s + NS * mr) << 16);
    }

    if (tid < 128) {
        const float4* src = isA ? (const float4*)&k_emb[rbase * 64]
                                : (const float4*)&v_emb[rbase * 64];
        ((float4*)x_s)[tid] = src[tid];
    }

    {
        const float4* s0 = isA ? (const float4*)Mk : (const float4*)eW;
        const float4* s1f = (const float4*)fW;
        const float4* s1a = (const float4*)aW;
        float4 v0[4], v1[4];
#pragma unroll
        for (int k = 0; k < 4; k++) {
            int i = tid + k * 256;
            int o = i >> 4, q4 = i & 15;
            v0[k] = s0[i];
            v1[k] = isA ? s1f[o * 32 + 16 + q4] : s1a[i];
        }
#pragma unroll
        for (int k = 0; k < 4; k++) {
            int i = tid + k * 256;
            int o = i >> 4, q4 = i & 15;
            *(float4*)&W0[o * 68 + q4 * 4] = v0[k];
            *(float4*)&W1[o * 68 + q4 * 4] = v1[k];
        }
    }
    __syncthreads();

    const float* Wm = mat ? W1 : W0;
    const float4* pL = (const float4*)&Wm[l * 68];
    const float4* pH = (const float4*)&Wm[(l + 32) * 68];
    const float4* xs0 = (const float4*)&x_s[pair * 2][0];
    const float4* xs1 = (const float4*)&x_s[pair * 2 + 1][0];

    float c0L = 0.f, c0H = 0.f, c1L = 0.f, c1H = 0.f;
    float d0L = 0.f, d0H = 0.f, d1L = 0.f, d1H = 0.f;
#pragma unroll
    for (int q = 0; q < 16; q += 2) {
        float4 xa0 = xs0[q];     float4 xb0 = xs0[q + 1];
        float4 xa1 = xs1[q];     float4 xb1 = xs1[q + 1];
        float4 mLa = pL[q];      float4 mLb = pL[q + 1];
        float4 mHa = pH[q];      float4 mHb = pH[q + 1];
        c0L = fmaf(xa0.x, mLa.x, c0L); c0L = fmaf(xa0.y, mLa.y, c0L);
        c0L = fmaf(xa0.z, mLa.z, c0L); c0L = fmaf(xa0.w, mLa.w, c0L);
        c0H = fmaf(xa0.x, mHa.x, c0H); c0H = fmaf(xa0.y, mHa.y, c0H);
        c0H = fmaf(xa0.z, mHa.z, c0H); c0H = fmaf(xa0.w, mHa.w, c0H);
        c1L = fmaf(xa1.x, mLa.x, c1L); c1L = fmaf(xa1.y, mLa.y, c1L);
        c1L = fmaf(xa1.z, mLa.z, c1L); c1L = fmaf(xa1.w, mLa.w, c1L);
        c1H = fmaf(xa1.x, mHa.x, c1H); c1H = fmaf(xa1.y, mHa.y, c1H);
        c1H = fmaf(xa1.z, mHa.z, c1H); c1H = fmaf(xa1.w, mHa.w, c1H);
        d0L = fmaf(xb0.x, mLb.x, d0L); d0L = fmaf(xb0.y, mLb.y, d0L);
        d0L = fmaf(xb0.z, mLb.z, d0L); d0L = fmaf(xb0.w, mLb.w, d0L);
        d0H = fmaf(xb0.x, mHb.x, d0H); d0H = fmaf(xb0.y, mHb.y, d0H);
        d0H = fmaf(xb0.z, mHb.z, d0H); d0H = fmaf(xb0.w, mHb.w, d0H);
        d1L = fmaf(xb1.x, mLb.x, d1L); d1L = fmaf(xb1.y, mLb.y, d1L);
        d1L = fmaf(xb1.z, mLb.z, d1L); d1L = fmaf(xb1.w, mLb.w, d1L);
        d1H = fmaf(xb1.x, mHb.x, d1H); d1H = fmaf(xb1.y, mHb.y, d1H);
        d1H = fmaf(xb1.z, mHb.z, d1H); d1H = fmaf(xb1.w, mHb.w, d1H);
    }
    float r0L = c0L + d0L, r0H = c0H + d0H;
    float r1L = c1L + d1L, r1H = c1H + d1H;

    int row0 = rbase + pair * 2;
    int row1 = row0 + 1;

    if (isA) {
        if (mat == 0) {
            float e00 = __expf(r0L), e01 = __expf(r0H);
            float e10 = __expf(r1L), e11 = __expf(r1H);
            float s0 = e00 + e01, s1 = e10 + e11;
#pragma unroll
            for (int o = 16; o; o >>= 1) {
                s0 += __shfl_xor_sync(~0u, s0, o);
                s1 += __shfl_xor_sync(~0u, s1, o);
            }
            float i0 = 1.0f / s0, i1 = 1.0f / s1;
            g_W[row0 * 64 + l]      = e00 * i0;
            g_W[row0 * 64 + 32 + l] = e01 * i0;
            g_W[row1 * 64 + l]      = e10 * i1;
            g_W[row1 * 64 + 32 + l] = e11 * i1;
        } else {
            float fbl = fb[l], fbh = fb[l + 32];
            g_G[row0 * 32 + l] = make_float2(r0L + fbl, r0H + fbh);
            g_G[row1 * 32 + l] = make_float2(r1L + fbl, r1H + fbh);
        }
    } else {
        int p0 = pair * 2, p1 = pair * 2 + 1;
        if (mat == 1) {
            float abl = ab[l], abh = ab[l + 32];
            xch[p0][l]      = tanhf(r0L + abl);
            xch[p0][l + 32] = tanhf(r0H + abh);
            xch[p1][l]      = tanhf(r1L + abl);
            xch[p1][l + 32] = tanhf(r1H + abh);
        }
        __syncthreads();
        if (mat == 0) {
            float ebl = eb[l], ebh = eb[l + 32];
            g_EA[row0 * 64 + l]      = make_float2(sigmoid_e(r0L + ebl), xch[p0][l]);
            g_EA[row0 * 64 + l + 32] = make_float2(sigmoid_e(r0H + ebh), xch[p0][l + 32]);
            g_EA[row1 * 64 + l]      = make_float2(sigmoid_e(r1L + ebl), xch[p1][l]);
            g_EA[row1 * 64 + l + 32] = make_float2(sigmoid_e(r1H + ebh), xch[p1][l + 32]);
        }
    }
}

// =====================================================================
// Kernel S: transposed scan. Block = (b, 32-d group), 8 warps; warp =
// m-octet; lane = d. State Mv[8] in registers per lane. w broadcast,
// read = in-register dot + cross-warp partial fold after the chunk bar.
// 128 blocks x 256 threads; 16-step chunks (12 full + 8-step tail).
// =====================================================================
__global__ __launch_bounds__(256) void k_scan(const float* __restrict__ Mv0)
{
    __shared__ __align__(16) float  w_sh[2][16][64];      //  8KB
    __shared__ __align__(16) float2 ea_sh[2][16][32];     //  8KB
    __shared__ __align__(16) float  part[2][16][8][32];   // 32KB

    int tid = threadIdx.x;
    int w = tid >> 5, l = tid & 31;
    int b = blockIdx.x >> 1;
    int dbase = (blockIdx.x & 1) << 5;
    int d = dbase + l;
    int woct = w << 3;                 // my m-octet base

    float mv[8];
#pragma unroll
    for (int j = 0; j < 8; j++) mv[j] = Mv0[(woct + j) * 64 + d];

    const int* idxp = g_idx + b * TT;
    float* rd = g_read + b * TT * 64 + d;

    int si = tid >> 4, qi = tid & 15;  // staging: step, quarter
    int dh = dbase >> 1;               // float4 offset into g_EA row

    // ---- prologue: stage chunk 0 into buffer 0
    {
        int p = idxp[si];
        float4 wr = ((const float4*)g_W)[(p & 0xffff) * 16 + qi];
        float4 er = ((const float4*)g_EA)[(p >> 16) * 32 + dh + qi];
        *(float4*)&w_sh[0][si][qi * 4] = wr;
        *(float4*)&ea_sh[0][si][qi * 2] = er;
    }
    __syncthreads();

#define SCAN_STEP(BUF, T)                                                     \
    do {                                                                      \
        float4 w0 = *(const float4*)&w_sh[BUF][T][woct];                      \
        float4 w1 = *(const float4*)&w_sh[BUF][T][woct + 4];                  \
        float2 ea = ea_sh[BUF][T][l];                                         \
        float ne = -ea.x, av = ea.y;                                          \
        float rA, rB, rC, rD;                                                 \
        rA = w0.x * mv[0]; rB = w0.y * mv[1];                                 \
        rC = w0.z * mv[2]; rD = w0.w * mv[3];                                 \
        float t0_ = fmaf(ne, mv[0], av); mv[0] = fmaf(w0.x, t0_, mv[0]);      \
        float t1_ = fmaf(ne, mv[1], av); mv[1] = fmaf(w0.y, t1_, mv[1]);      \
        float t2_ = fmaf(ne, mv[2], av); mv[2] = fmaf(w0.z, t2_, mv[2]);      \
        float t3_ = fmaf(ne, mv[3], av); mv[3] = fmaf(w0.w, t3_, mv[3]);      \
        rA = fmaf(w1.x, mv[4], rA); rB = fmaf(w1.y, mv[5], rB);               \
        rC = fmaf(w1.z, mv[6], rC); rD = fmaf(w1.w, mv[7], rD);               \
        float t4_ = fmaf(ne, mv[4], av); mv[4] = fmaf(w1.x, t4_, mv[4]);      \
        float t5_ = fmaf(ne, mv[5], av); mv[5] = fmaf(w1.y, t5_, mv[5]);      \
        float t6_ = fmaf(ne, mv[6], av); mv[6] = fmaf(w1.z, t6_, mv[6]);      \
        float t7_ = fmaf(ne, mv[7], av); mv[7] = fmaf(w1.w, t7_, mv[7]);      \
        part[BUF][T][w][l] = (rA + rB) + (rC + rD);                           \
    } while (0)

    for (int c = 0; c < 12; c++) {
        int cur = c & 1;

        // ---- fold previous chunk's partials -> g_read
        if (c > 0) {
            int pb = cur ^ 1;
            int pt0 = (c - 1) * 16;
#pragma unroll
            for (int rr = 0; rr < 2; rr++) {
                int ss = w + rr * 8;
                const float* pp = &part[pb][ss][0][l];
                float sum = ((pp[0] + pp[32]) + (pp[64] + pp[96]))
                          + ((pp[128] + pp[160]) + (pp[192] + pp[224]));
                rd[(pt0 + ss) * 64] = sum;
            }
        }

        // ---- stage chunk c+1 into registers
        float4 wr, er;
        {
            int t0n = (c + 1) * 16;
            int sic = (c == 11 && si >= 8) ? 7 : si;
            int p = idxp[t0n + sic];
            wr = ((const float4*)g_W)[(p & 0xffff) * 16 + qi];
            er = ((const float4*)g_EA)[(p >> 16) * 32 + dh + qi];
        }

        // ---- compute chunk c (16 steps)
#pragma unroll
        for (int t = 0; t < 16; t++) SCAN_STEP(cur, t);

        // ---- commit staged registers
        *(float4*)&w_sh[cur ^ 1][si][qi * 4] = wr;
        *(float4*)&ea_sh[cur ^ 1][si][qi * 2] = er;
        __syncthreads();
    }

    // ---- epilogue: fold chunk 11, compute tail chunk 12 (8 steps)
    {
        int pt0 = 11 * 16;
#pragma unroll
        for (int rr = 0; rr < 2; rr++) {
            int ss = w + rr * 8;
            const float* pp = &part[1][ss][0][l];
            float sum = ((pp[0] + pp[32]) + (pp[64] + pp[96]))
                      + ((pp[128] + pp[160]) + (pp[192] + pp[224]));
            rd[(pt0 + ss) * 64] = sum;
        }
#pragma unroll
        for (int t = 0; t < 8; t++) SCAN_STEP(0, t);
        __syncthreads();
        {
            const float* pp = &part[0][w][0][l];
            float sum = ((pp[0] + pp[32]) + (pp[64] + pp[96]))
                      + ((pp[128] + pp[160]) + (pp[192] + pp[224]));
            rd[(192 + w) * 64] = sum;
        }
    }
#undef SCAN_STEP
}

// =====================================================================
// Kernel O: 4 rows per warp (R16 version verbatim).
// =====================================================================
__global__ __launch_bounds__(256, 5) void k_out(
    const float* __restrict__ fW, const float* __restrict__ pW,
    const float* __restrict__ pb, float* __restrict__ out)
{
    __shared__ __align__(16) float F1[64 * 68];
    __shared__ __align__(16) float x_s[8][4][64];

    int tid = threadIdx.x;
    {
        const float4* src = (const float4*)fW;
#pragma unroll
        for (int k = 0; k < 4; k++) {
            int i = tid + k * 256;
            int o = i >> 4, q4 = i & 15;
            *(float4*)&F1[o * 68 + q4 * 4] = src[o * 32 + q4];
        }
    }
    __syncthreads();

    int w = tid >> 5, l = tid & 31;
    const float4* pL = (const float4*)&F1[l * 68];
    const float4* pH = (const float4*)&F1[(l + 32) * 68];
    float pl = pW[l], ph = pW[l + 32];
    float pbv = pb[0];

    int rowb = blockIdx.x * 32 + w * 4;
    int iidx[4];
#pragma unroll
    for (int r = 0; r < 4; r++) {
        int row = rowb + r;
        int b0 = row / 199, t0 = row - b0 * 199 + 1;
        iidx[r] = b0 * TT + t0;
        *(float2*)&x_s[w][r][2 * l] = ((const float2*)&g_read[iidx[r] * 64])[l];
    }
    __syncwarp();

    float aL[4] = {0.f, 0.f, 0.f, 0.f};
    float aH[4] = {0.f, 0.f, 0.f, 0.f};
#pragma unroll
    for (int q = 0; q < 16; q++) {
        float4 mL = pL[q];
        float4 mH = pH[q];
#pragma unroll
        for (int r = 0; r < 4; r++) {
            float4 xa = *(const float4*)&x_s[w][r][q * 4];
            aL[r] = fmaf(xa.x, mL.x, aL[r]); aL[r] = fmaf(xa.y, mL.y, aL[r]);
            aL[r] = fmaf(xa.z, mL.z, aL[r]); aL[r] = fmaf(xa.w, mL.w, aL[r]);
            aH[r] = fmaf(xa.x, mH.x, aH[r]); aH[r] = fmaf(xa.y, mH.y, aH[r]);
            aH[r] = fmaf(xa.z, mH.z, aH[r]); aH[r] = fmaf(xa.w, mH.w, aH[r]);
        }
    }

    float rv[4];
#pragma unroll
    for (int r = 0; r < 4; r++) {
        int sk = g_idx[iidx[r]] & 0xffff;
        float2 G = g_G[sk * 32 + l];
        float fL = tanh_a(aL[r] + G.x);
        float fH = tanh_a(aH[r] + G.y);
        rv[r] = fL * pl + fH * ph;
    }
#pragma unroll
    for (int o = 16; o; o >>= 1) {
#pragma unroll
        for (int r = 0; r < 4; r++)
            rv[r] += __shfl_xor_sync(~0u, rv[r], o);
    }
    if (l == 0) {
#pragma unroll
        for (int r = 0; r < 4; r++)
            out[rowb + r] = sigmoid_e(rv[r] + pbv);
    }
}

// =====================================================================
// launch
// =====================================================================
extern "C" void kernel_launch(void* const* d_in, const int* in_sizes, int n_in,
                              void* d_out, int out_size) {
    const int*   skills    = (const int*)d_in[0];
    const int*   responses = (const int*)d_in[1];
    const float* k_emb     = (const float*)d_in[2];
    const float* v_emb     = (const float*)d_in[3];
    const float* Mk        = (const float*)d_in[4];
    const float* Mv0       = (const float*)d_in[5];
    const float* fW        = (const float*)d_in[6];
    const float* fb        = (const float*)d_in[7];
    const float* eW        = (const float*)d_in[8];
    const float* eb        = (const float*)d_in[9];
    const float* aW        = (const float*)d_in[10];
    const float* ab        = (const float*)d_in[11];
    const float* pW        = (const float*)d_in[12];
    const float* pb        = (const float*)d_in[13];
    float* out = (float*)d_out;

    k_pre <<<375, 256>>>(skills, responses, k_emb, v_emb, Mk, fW, fb, eW, eb, aW, ab);
    k_scan<<<128, 256>>>(Mv0);
    k_out <<<398, 256>>>(fW, pW, pb, out);
}